// round 13
// baseline (speedup 1.0000x reference)
#include <cuda_runtime.h>
#include <cuda_bf16.h>
#include <math.h>

#define SCALE_F 0.125f
#define EPS_F 1e-5f

// ---------------- scratch (device globals) ----------------
__device__ unsigned g_wu[2048 * 512];       // w packed bf16x2 [row][k/2]
__device__ unsigned g_ru[1024 * 512];       // r packed bf16x2
__device__ unsigned g_WqkvT[3072 * 512];    // W_qkv^T bf16x2 [n][k/2]
__device__ unsigned g_WrfwT[1024 * 512];    // W_r_fw^T bf16x2
__device__ unsigned g_WrbwT[1024 * 512];    // W_r_bw^T bf16x2
__device__ unsigned g_WoT[1024 * 512];      // W_o^T bf16x2
__device__ unsigned g_q1u[32 * 1024 * 32];  // q + r_w_bias, bf16x2 [z][i][32]
__device__ unsigned g_q2u[32 * 1024 * 32];  // q + r_r_bias, bf16x2
__device__ unsigned g_kku[32 * 1024 * 32];  // k heads, bf16x2
__device__ float    g_vv[32 * 1024 * 64];   // v heads fp32 [z][i][64]
__device__ unsigned g_vvt[32 * 64 * 512];   // v transposed bf16x2 [z][d][j/2]
__device__ unsigned g_rku[2048 * 512];      // r_k bf16x2 [jr][512] (row 2047 zeroed)
__device__ __nv_bfloat16 g_bdh[67108864];   // BD bf16 [z][1024][2048] (band only)
__device__ unsigned g_vecu[2048 * 512];     // attn vec bf16x2 [(i*2+b)][(n*64+d)/2]
__device__ float    g_x[2048 * 1024];       // vec @ W_o fp32

// ---------------- helpers ----------------
__device__ __forceinline__ void cp16(void* s, const void* g) {
    unsigned a = (unsigned)__cvta_generic_to_shared(s);
    asm volatile("cp.async.cg.shared.global [%0], [%1], 16;\n" ::"r"(a), "l"(g));
}
__device__ __forceinline__ unsigned packbf(float lo, float hi) {
    unsigned u;
    asm("cvt.rn.bf16x2.f32 %0, %1, %2;" : "=r"(u) : "f"(hi), "f"(lo));
    return u;
}
// bf16x2 rows of 32 u32 (=64 bf16), XOR swizzle
__device__ __forceinline__ int adru(int r, int c) {
    return r * 32 + (((c >> 2) ^ (r & 7)) << 2) + (c & 3);
}
#define MMA_BF16(c, a, b)                                                          \
    asm volatile(                                                                  \
        "mma.sync.aligned.m16n8k16.row.col.f32.bf16.bf16.f32 "                     \
        "{%0,%1,%2,%3},{%4,%5,%6,%7},{%8,%9},{%0,%1,%2,%3};"                       \
        : "+f"(c[0]), "+f"(c[1]), "+f"(c[2]), "+f"(c[3])                           \
        : "r"(a[0]), "r"(a[1]), "r"(a[2]), "r"(a[3]), "r"(b[0]), "r"(b[1]))

// ---------------- merged prep: packs + transposes + zero pad ----------------
__device__ __forceinline__ void packT_body2(const float* in, unsigned* out, int N,
                                            int n0, int k0, float (*ts)[65]) {
    int t = threadIdx.x;
#pragma unroll
    for (int e = 0; e < 16; e++) {
        int idx = e * 256 + t, kk = idx >> 6, nn = idx & 63;
        ts[kk][nn] = in[(long long)(k0 + kk) * N + n0 + nn];
    }
    __syncthreads();
#pragma unroll
    for (int e = 0; e < 8; e++) {
        int idx = e * 256 + t, nn = idx >> 5, kp = idx & 31;
        out[(long long)(n0 + nn) * 512 + (k0 >> 1) + kp] =
            packbf(ts[2 * kp][nn], ts[2 * kp + 1][nn]);
    }
}
__global__ __launch_bounds__(256) void prep_k(
    const float* __restrict__ w, unsigned* __restrict__ wu,
    const float* __restrict__ r, unsigned* __restrict__ ru,
    const float* __restrict__ Wqkv, unsigned* __restrict__ WqkvT,
    const float* __restrict__ Wrfw, unsigned* __restrict__ WrfwT,
    const float* __restrict__ Wrbw, unsigned* __restrict__ WrbwT,
    const float* __restrict__ Wo, unsigned* __restrict__ WoT,
    unsigned* __restrict__ rkpad) {
    __shared__ float ts[64][65];
    int b = blockIdx.x;
    if (b < 4096) {
        int i = b * 256 + threadIdx.x;
        float2 v = ((const float2*)w)[i];
        wu[i] = packbf(v.x, v.y);
    } else if (b < 6144) {
        int i = (b - 4096) * 256 + threadIdx.x;
        float2 v = ((const float2*)r)[i];
        ru[i] = packbf(v.x, v.y);
    } else if (b < 6912) {
        int idx = b - 6144;  // 768 = 48 x 16
        packT_body2(Wqkv, WqkvT, 3072, (idx % 48) * 64, (idx / 48) * 64, ts);
    } else if (b < 7680) {
        int idx = b - 6912;  // 768 = 256 x 3
        int zsel = idx >> 8; idx &= 255;
        const float* in = (zsel == 0) ? Wrfw : (zsel == 1) ? Wrbw : Wo;
        unsigned* outp = (zsel == 0) ? WrfwT : (zsel == 1) ? WrbwT : WoT;
        packT_body2(in, outp, 1024, (idx & 15) * 64, (idx >> 4) * 64, ts);
    } else {
        rkpad[(b - 7680) * 256 + threadIdx.x] = 0u;  // zero rku row 2047 (2 blocks)
    }
}

// ---------------- bf16 GEMM 128x128, both operands u32 [rows][k/2] ----------------
// EPI 0: plain fp32 store to f4 (ldc=1024). EPI 2: QKV head scatter. EPI 3: rk.
template <int EPI>
__global__ __launch_bounds__(256, 2) void bgemm_k(
    const unsigned* __restrict__ A, const unsigned* __restrict__ B,
    int KU, int ldau, int ldbu,
    const unsigned* __restrict__ B2,
    const float* __restrict__ bias1, const float* __restrict__ bias2,
    unsigned* __restrict__ u1, unsigned* __restrict__ u2, unsigned* __restrict__ u3,
    float* __restrict__ f4) {
    extern __shared__ unsigned su[];
    int t = threadIdx.x, lane = t & 31, lq = lane & 3, lr = lane >> 2;
    int row0 = blockIdx.y * 128;
    int col0 = (EPI == 3) ? (blockIdx.x & 7) * 128 : blockIdx.x * 128;
    bool bw = (EPI == 3) && (blockIdx.x >= 8);
    if (bw) B = B2;
    int warp = t >> 5, wm = warp >> 1, wn = warp & 1;

    float acc[2][8][4] = {};

    auto load_tile = [&](int kt, int st) {
        unsigned* sA = su + st * 8192;
        unsigned* sB = sA + 4096;
        int k0 = kt * 32;
#pragma unroll
        for (int e = 0; e < 4; e++) {
            int c = e * 256 + t, r = c >> 3, c4 = c & 7;
            cp16(sA + r * 32 + ((c4 ^ (r & 7)) << 2),
                 A + (long long)(row0 + r) * ldau + k0 + c4 * 4);
            cp16(sB + r * 32 + ((c4 ^ (r & 7)) << 2),
                 B + (long long)(col0 + r) * ldbu + k0 + c4 * 4);
        }
        asm volatile("cp.async.commit_group;\n");
    };

    load_tile(0, 0);
    int KT = KU >> 5;
    for (int kt = 0; kt < KT; kt++) {
        int st = kt & 1;
        if (kt + 1 < KT) {
            load_tile(kt + 1, st ^ 1);
            asm volatile("cp.async.wait_group 1;\n");
        } else {
            asm volatile("cp.async.wait_group 0;\n");
        }
        __syncthreads();
        unsigned* sA = su + st * 8192;
        unsigned* sB = sA + 4096;
#pragma unroll
        for (int s = 0; s < 4; s++) {
            unsigned af[2][4], bf[8][2];
#pragma unroll
            for (int mt = 0; mt < 2; mt++) {
                int r = wm * 32 + mt * 16 + lr;
                af[mt][0] = sA[adru(r, s * 8 + lq)];
                af[mt][1] = sA[adru(r + 8, s * 8 + lq)];
                af[mt][2] = sA[adru(r, s * 8 + 4 + lq)];
                af[mt][3] = sA[adru(r + 8, s * 8 + 4 + lq)];
            }
#pragma unroll
            for (int nt = 0; nt < 8; nt++) {
                int nn = wn * 64 + nt * 8 + lr;
                bf[nt][0] = sB[adru(nn, s * 8 + lq)];
                bf[nt][1] = sB[adru(nn, s * 8 + 4 + lq)];
            }
#pragma unroll
            for (int mt = 0; mt < 2; mt++)
#pragma unroll
                for (int nt = 0; nt < 8; nt++) MMA_BF16(acc[mt][nt], af[mt], bf[nt]);
        }
        __syncthreads();
    }

#pragma unroll
    for (int mt = 0; mt < 2; mt++)
#pragma unroll
        for (int nt = 0; nt < 8; nt++) {
            int r0 = row0 + wm * 32 + mt * 16 + lr;
            int cb = col0 + wn * 64 + nt * 8 + 2 * lq;
#pragma unroll
            for (int pe = 0; pe < 2; pe++) {
                int rr = r0 + pe * 8;
                float v0 = acc[mt][nt][pe * 2], v1 = acc[mt][nt][pe * 2 + 1];
                if (EPI == 0) {
                    f4[(long long)rr * 1024 + cb] = v0;
                    f4[(long long)rr * 1024 + cb + 1] = v1;
                } else if (EPI == 3) {
                    if (bw) {
                        if (rr == 1023) continue;  // fw owns rk row 1023
                        u2[(long long)rr * (-512) + (cb >> 1)] = packbf(v0, v1);
                    } else {
                        u1[(long long)rr * 512 + (cb >> 1)] = packbf(v0, v1);
                    }
                } else {  // EPI == 2: QKV scatter
                    int i = rr >> 1, bb = rr & 1;
                    int sec = cb >> 10, c1 = cb & 1023, n = c1 >> 6, d = c1 & 63;
                    int z = bb * 16 + n;
                    if (sec == 0) {
                        long long idx = ((long long)z << 15) + (i << 5) + (d >> 1);
                        u1[idx] = packbf(v0 + bias1[c1], v1 + bias1[c1 + 1]);
                        u2[idx] = packbf(v0 + bias2[c1], v1 + bias2[c1 + 1]);
                    } else if (sec == 1) {
                        u3[((long long)z << 15) + (i << 5) + (d >> 1)] = packbf(v0, v1);
                    } else {
                        long long idx = ((long long)z << 16) + (i << 6) + d;
                        f4[idx] = v0; f4[idx + 1] = v1;
                    }
                }
            }
        }
}

// ---------------- V transpose: vv[z][j][d] fp32 -> vvt[z][d][j/2] bf16x2 ----------------
__global__ __launch_bounds__(256) void vt_k(const float* __restrict__ vv,
                                            unsigned* __restrict__ vvt) {
    __shared__ float ts[128][65];
    int t = threadIdx.x, z = blockIdx.y, j0 = blockIdx.x * 128;
    const float* Vz = vv + ((long long)z << 16);
#pragma unroll
    for (int e = 0; e < 8; e++) {
        int idx = e * 256 + t, r = idx >> 4, c4 = idx & 15;
        float4 v = *(const float4*)(Vz + (long long)(j0 + r) * 64 + c4 * 4);
        ts[r][c4 * 4] = v.x; ts[r][c4 * 4 + 1] = v.y;
        ts[r][c4 * 4 + 2] = v.z; ts[r][c4 * 4 + 3] = v.w;
    }
    __syncthreads();
#pragma unroll
    for (int e = 0; e < 16; e++) {
        int idx = e * 256 + t, d = idx >> 6, jp = idx & 63;
        vvt[((long long)z << 15) + (d << 9) + (j0 >> 1) + jp] =
            packbf(ts[jp * 2][d], ts[jp * 2 + 1][d]);
    }
}

// ---------------- bf16 BD band GEMM -> bf16 output (packed u32 stores) ----------------
__global__ __launch_bounds__(256, 2) void bd_k(
    const unsigned* __restrict__ q2, const unsigned* __restrict__ rk,
    unsigned* __restrict__ bdu) {
    __shared__ unsigned su[2 * 4096];
    unsigned* sA = su;
    unsigned* sB = su + 4096;
    int t = threadIdx.x, lane = t & 31, lq = lane & 3, lr = lane >> 2;
    int z = blockIdx.z;
    const unsigned* Az = q2 + ((long long)z << 15);
    const unsigned* Bz = rk + (long long)(z & 15) * 32;
    unsigned* Cz = bdu + ((long long)z << 20);
    int row0 = blockIdx.y * 128;
    int col0 = 896 - row0 + blockIdx.x * 128;
    int warp = t >> 5, wm = warp >> 1, wn = warp & 1;

#pragma unroll
    for (int e = 0; e < 4; e++) {
        int c = e * 256 + t, r = c >> 3, c4 = c & 7;
        cp16(sA + r * 32 + ((c4 ^ (r & 7)) << 2), Az + (long long)(row0 + r) * 32 + c4 * 4);
        cp16(sB + r * 32 + ((c4 ^ (r & 7)) << 2), Bz + (long long)(col0 + r) * 512 + c4 * 4);
    }
    asm volatile("cp.async.commit_group;\ncp.async.wait_group 0;\n");
    __syncthreads();

    float acc[2][8][4] = {};
#pragma unroll
    for (int s = 0; s < 4; s++) {
        unsigned af[2][4], bf[8][2];
#pragma unroll
        for (int mt = 0; mt < 2; mt++) {
            int r = wm * 32 + mt * 16 + lr;
            af[mt][0] = sA[adru(r, s * 8 + lq)];
            af[mt][1] = sA[adru(r + 8, s * 8 + lq)];
            af[mt][2] = sA[adru(r, s * 8 + 4 + lq)];
            af[mt][3] = sA[adru(r + 8, s * 8 + 4 + lq)];
        }
#pragma unroll
        for (int nt = 0; nt < 8; nt++) {
            int nn = wn * 64 + nt * 8 + lr;
            bf[nt][0] = sB[adru(nn, s * 8 + lq)];
            bf[nt][1] = sB[adru(nn, s * 8 + 4 + lq)];
        }
#pragma unroll
        for (int mt = 0; mt < 2; mt++)
#pragma unroll
            for (int nt = 0; nt < 8; nt++) MMA_BF16(acc[mt][nt], af[mt], bf[nt]);
    }

#pragma unroll
    for (int mt = 0; mt < 2; mt++)
#pragma unroll
        for (int nt = 0; nt < 8; nt++) {
            int r0 = row0 + wm * 32 + mt * 16 + lr;
            int cb = col0 + wn * 64 + nt * 8 + 2 * lq;
#pragma unroll
            for (int pe = 0; pe < 2; pe++) {
                int rr = r0 + pe * 8;
                Cz[((rr << 11) + cb) >> 1] = packbf(acc[mt][nt][pe * 2], acc[mt][nt][pe * 2 + 1]);
            }
        }
}

// ---------------- flash (bf16): S = Q1·K^T + BD_band, mask, online softmax, P·V ----------------
__global__ __launch_bounds__(256, 2) void flash_k(
    const unsigned* __restrict__ q1, const unsigned* __restrict__ kk,
    const unsigned* __restrict__ vvt, const __nv_bfloat16* __restrict__ bdh,
    const unsigned char* __restrict__ mask, unsigned* __restrict__ vecu) {
    extern __shared__ unsigned fsu[];
    unsigned* sQ = fsu;                   // 128 x 32 u32
    unsigned* sP = sQ + 4096;             // 128 x 32 u32
    unsigned* sK = sP + 4096;             // 3 x 64 x 32 u32
    unsigned* sVt = sK + 3 * 2048;        // 3 x 64 x 32 u32 (rows = d)
    float* sMask = (float*)(sVt + 3 * 2048);  // 1024 flags

    int t = threadIdx.x, lane = t & 31, warp = t >> 5;
    int lq = lane & 3, lr = lane >> 2;
    int i0 = blockIdx.x * 128, z = blockIdx.y, b = z >> 4, nh = z & 15;
    const unsigned* Qz = q1 + ((long long)z << 15);
    const unsigned* Kz = kk + ((long long)z << 15);
    const unsigned* Vtz = vvt + ((long long)z << 15);
    const __nv_bfloat16* bdz = bdh + ((long long)z << 21);

    for (int e = t; e < 1024; e += 256) sMask[e] = mask[e * 2 + b] ? 1.0f : 0.0f;

#pragma unroll
    for (int e = 0; e < 4; e++) {
        int c = e * 256 + t, r = c >> 3, c4 = c & 7;
        cp16(sQ + r * 32 + ((c4 ^ (r & 7)) << 2), Qz + (long long)(i0 + r) * 32 + c4 * 4);
    }
    auto loadKV = [&](int jt, int bufi) {
        unsigned* dK = sK + bufi * 2048;
        unsigned* dV = sVt + bufi * 2048;
        int j0 = jt * 64;
#pragma unroll
        for (int e = 0; e < 2; e++) {
            int c = e * 256 + t, r = c >> 3, c4 = c & 7;
            cp16(dK + r * 32 + ((c4 ^ (r & 7)) << 2), Kz + (long long)(j0 + r) * 32 + c4 * 4);
            cp16(dV + r * 32 + ((c4 ^ (r & 7)) << 2),
                 Vtz + ((long long)r << 9) + (j0 >> 1) + c4 * 4);
        }
        asm volatile("cp.async.commit_group;\n");
    };
    loadKV(0, 0);
    loadKV(1, 1);

    float mA = -3.4e38f, mB = -3.4e38f, lA = 0.f, lB = 0.f;
    float O[8][4] = {};
    int rb = warp * 16 + lr;
    int rowA = i0 + rb;
    const unsigned short* bd0 = (const unsigned short*)(bdz + (long long)rowA * 2048 + (1023 - rowA));
    const unsigned short* bd1 = (const unsigned short*)(bdz + (long long)(rowA + 8) * 2048 + (1015 - rowA));

    // BD prefetch for one tile ahead: 16 packed u32 regs (lo|hi<<16)
    unsigned pbv[16];
    auto prefetchBD = [&](int jt) {
#pragma unroll
        for (int nt = 0; nt < 8; nt++) {
            int jc = jt * 64 + nt * 8 + 2 * lq;
            unsigned short l0 = __ldg(bd0 + jc), h0 = __ldg(bd0 + jc + 1);
            unsigned short l1 = __ldg(bd1 + jc), h1 = __ldg(bd1 + jc + 1);
            pbv[2 * nt] = (unsigned)l0 | ((unsigned)h0 << 16);
            pbv[2 * nt + 1] = (unsigned)l1 | ((unsigned)h1 << 16);
        }
    };
    prefetchBD(0);

    for (int jt = 0; jt < 16; jt++) {
        int buf = jt % 3;
        if (jt == 15) asm volatile("cp.async.wait_group 0;\n");
        else          asm volatile("cp.async.wait_group 1;\n");
        __syncthreads();

        // ---- S = Q1 @ K^T ----
        unsigned* cK = sK + buf * 2048;
        float S[8][4] = {};
#pragma unroll
        for (int s = 0; s < 4; s++) {
            unsigned a[4];
            a[0] = sQ[adru(rb, s * 8 + lq)];
            a[1] = sQ[adru(rb + 8, s * 8 + lq)];
            a[2] = sQ[adru(rb, s * 8 + 4 + lq)];
            a[3] = sQ[adru(rb + 8, s * 8 + 4 + lq)];
#pragma unroll
            for (int nt = 0; nt < 8; nt++) {
                int nn = nt * 8 + lr;
                unsigned bfx[2];
                bfx[0] = cK[adru(nn, s * 8 + lq)];
                bfx[1] = cK[adru(nn, s * 8 + 4 + lq)];
                MMA_BF16(S[nt], a, bfx);
            }
        }

        // ---- combine prefetched BD, scale, mask ----
        int j0 = jt * 64;
#pragma unroll
        for (int nt = 0; nt < 8; nt++) {
            int jc = j0 + nt * 8 + 2 * lq;
            float2 f0 = __bfloat1622float2(*reinterpret_cast<__nv_bfloat162*>(&pbv[2 * nt]));
            float2 f1 = __bfloat1622float2(*reinterpret_cast<__nv_bfloat162*>(&pbv[2 * nt + 1]));
            float s0 = (S[nt][0] + f0.x) * SCALE_F;
            float s1 = (S[nt][1] + f0.y) * SCALE_F;
            float s2 = (S[nt][2] + f1.x) * SCALE_F;
            float s3 = (S[nt][3] + f1.y) * SCALE_F;
            if (sMask[jc] != 0.f)     { s0 = -1e30f; s2 = -1e30f; }
            if (sMask[jc + 1] != 0.f) { s1 = -1e30f; s3 = -1e30f; }
            S[nt][0] = s0; S[nt][1] = s1; S[nt][2] = s2; S[nt][3] = s3;
        }

        // ---- online softmax ----
        float mxA = -3.4e38f, mxB = -3.4e38f;
#pragma unroll
        for (int nt = 0; nt < 8; nt++) {
            mxA = fmaxf(mxA, fmaxf(S[nt][0], S[nt][1]));
            mxB = fmaxf(mxB, fmaxf(S[nt][2], S[nt][3]));
        }
        mxA = fmaxf(mxA, __shfl_xor_sync(0xffffffffu, mxA, 1));
        mxA = fmaxf(mxA, __shfl_xor_sync(0xffffffffu, mxA, 2));
        mxB = fmaxf(mxB, __shfl_xor_sync(0xffffffffu, mxB, 1));
        mxB = fmaxf(mxB, __shfl_xor_sync(0xffffffffu, mxB, 2));
        float nmA = fmaxf(mA, mxA), nmB = fmaxf(mB, mxB);
        float scA = __expf(mA - nmA), scB = __expf(mB - nmB);
        mA = nmA; mB = nmB;
        float smA = 0.f, smB = 0.f;
#pragma unroll
        for (int nt = 0; nt < 8; nt++) {
            float p0 = __expf(S[nt][0] - nmA), p1 = __expf(S[nt][1] - nmA);
            float p2 = __expf(S[nt][2] - nmB), p3 = __expf(S[nt][3] - nmB);
            smA += p0 + p1; smB += p2 + p3;
            sP[adru(rb, nt * 4 + lq)] = packbf(p0, p1);
            sP[adru(rb + 8, nt * 4 + lq)] = packbf(p2, p3);
        }
        smA += __shfl_xor_sync(0xffffffffu, smA, 1);
        smA += __shfl_xor_sync(0xffffffffu, smA, 2);
        smB += __shfl_xor_sync(0xffffffffu, smB, 1);
        smB += __shfl_xor_sync(0xffffffffu, smB, 2);
        lA = lA * scA + smA;
        lB = lB * scB + smB;
#pragma unroll
        for (int nt = 0; nt < 8; nt++) {
            O[nt][0] *= scA; O[nt][1] *= scA;
            O[nt][2] *= scB; O[nt][3] *= scB;
        }
        __syncwarp();  // sP rows are warp-private

        // ---- O += P @ V ----
        unsigned* cV = sVt + buf * 2048;
#pragma unroll
        for (int s = 0; s < 4; s++) {
            unsigned a[4];
            a[0] = sP[adru(rb, s * 8 + lq)];
            a[1] = sP[adru(rb + 8, s * 8 + lq)];
            a[2] = sP[adru(rb, s * 8 + 4 + lq)];
            a[3] = sP[adru(rb + 8, s * 8 + 4 + lq)];
#pragma unroll
            for (int nt = 0; nt < 8; nt++) {
                int nn = nt * 8 + lr;
                unsigned bfx[2];
                bfx[0] = cV[adru(nn, s * 8 + lq)];
                bfx[1] = cV[adru(nn, s * 8 + 4 + lq)];
                MMA_BF16(O[nt], a, bfx);
            }
        }

        if (jt + 2 < 16) loadKV(jt + 2, (jt + 2) % 3);
        if (jt + 1 < 16) prefetchBD(jt + 1);  // S regs dead here; hides BD latency
    }

    // ---- finalize: normalize, pack bf16x2, store vec ----
    float iA = 1.0f / lA, iB = 1.0f / lB;
#pragma unroll
    for (int nt = 0; nt < 8; nt++) {
        int cp = (nh << 5) + nt * 4 + lq;  // pair column index
        vecu[(((long long)(rowA * 2 + b)) << 9) + cp] = packbf(O[nt][0] * iA, O[nt][1] * iA);
        vecu[(((long long)((rowA + 8) * 2 + b)) << 9) + cp] = packbf(O[nt][2] * iB, O[nt][3] * iB);
    }
}

// ---------------- residual + LayerNorm (float4) ----------------
__global__ void ln_k(const float* __restrict__ w, const float* __restrict__ xb,
                     const float* __restrict__ g, const float* __restrict__ bb,
                     float* __restrict__ out) {
    __shared__ float smr[16];
    int row = blockIdx.x, t = threadIdx.x;
    const float4* wr = (const float4*)(w + (long long)row * 1024);
    const float4* xr = (const float4*)(xb + (long long)row * 1024);
    float4 wv = wr[t], xv = xr[t];
    float l0 = wv.x + xv.x, l1 = wv.y + xv.y, l2 = wv.z + xv.z, l3 = wv.w + xv.w;
    float s = l0 + l1 + l2 + l3;
    float sq = l0 * l0 + l1 * l1 + l2 * l2 + l3 * l3;
#pragma unroll
    for (int o = 16; o; o >>= 1) {
        s += __shfl_xor_sync(0xffffffffu, s, o);
        sq += __shfl_xor_sync(0xffffffffu, sq, o);
    }
    if ((t & 31) == 0) { smr[t >> 5] = s; smr[8 + (t >> 5)] = sq; }
    __syncthreads();
    s = smr[t & 7]; sq = smr[8 + (t & 7)];
#pragma unroll
    for (int o = 4; o; o >>= 1) {
        s += __shfl_xor_sync(0xffffffffu, s, o);
        sq += __shfl_xor_sync(0xffffffffu, sq, o);
    }
    float mu = s * (1.0f / 1024.0f);
    float var = sq * (1.0f / 1024.0f) - mu * mu;
    float rstd = rsqrtf(var + EPS_F);
    float4 gv = ((const float4*)g)[t];
    float4 bv = ((const float4*)bb)[t];
    float4 ov;
    ov.x = (l0 - mu) * rstd * gv.x + bv.x;
    ov.y = (l1 - mu) * rstd * gv.y + bv.y;
    ov.z = (l2 - mu) * rstd * gv.z + bv.z;
    ov.w = (l3 - mu) * rstd * gv.w + bv.w;
    ((float4*)(out + (long long)row * 1024))[t] = ov;
}

// ---------------- launch ----------------
extern "C" void kernel_launch(void* const* d_in, const int* in_sizes, int n_in,
                              void* d_out, int out_size) {
    const float* w    = (const float*)d_in[0];
    const float* r    = (const float*)d_in[1];
    const float* rwb  = (const float*)d_in[2];
    const float* rrb  = (const float*)d_in[3];
    const unsigned char* mask = (const unsigned char*)d_in[4];
    const float* Wqkv = (const float*)d_in[5];
    const float* Wrfw = (const float*)d_in[6];
    const float* Wrbw = (const float*)d_in[7];
    const float* Wo   = (const float*)d_in[8];
    const float* lng  = (const float*)d_in[9];
    const float* lnb  = (const float*)d_in[10];
    float* out = (float*)d_out;

    unsigned *wu, *ru, *WqkvT, *WrfwT, *WrbwT, *WoT;
    unsigned *q1u, *q2u, *kku, *rku, *vvt, *vecu;
    __nv_bfloat16* bdh;
    float *vv, *xb;
    cudaGetSymbolAddress((void**)&wu, g_wu);
    cudaGetSymbolAddress((void**)&ru, g_ru);
    cudaGetSymbolAddress((void**)&WqkvT, g_WqkvT);
    cudaGetSymbolAddress((void**)&WrfwT, g_WrfwT);
    cudaGetSymbolAddress((void**)&WrbwT, g_WrbwT);
    cudaGetSymbolAddress((void**)&WoT, g_WoT);
    cudaGetSymbolAddress((void**)&q1u, g_q1u);
    cudaGetSymbolAddress((void**)&q2u, g_q2u);
    cudaGetSymbolAddress((void**)&kku, g_kku);
    cudaGetSymbolAddress((void**)&vv, g_vv);
    cudaGetSymbolAddress((void**)&vvt, g_vvt);
    cudaGetSymbolAddress((void**)&rku, g_rku);
    cudaGetSymbolAddress((void**)&bdh, g_bdh);
    cudaGetSymbolAddress((void**)&vecu, g_vecu);
    cudaGetSymbolAddress((void**)&xb, g_x);

    // merged prep: pack w/r, transpose-pack all weights, zero rku pad row
    prep_k<<<7682, 256>>>(w, wu, r, ru, Wqkv, WqkvT, Wrfw, WrfwT,
                          Wrbw, WrbwT, Wo, WoT, rku + 2047 * 512);

    int bg_smem = 2 * 8192 * 4;  // 64 KB
    cudaFuncSetAttribute(bgemm_k<0>, cudaFuncAttributeMaxDynamicSharedMemorySize, bg_smem);
    cudaFuncSetAttribute(bgemm_k<2>, cudaFuncAttributeMaxDynamicSharedMemorySize, bg_smem);
    cudaFuncSetAttribute(bgemm_k<3>, cudaFuncAttributeMaxDynamicSharedMemorySize, bg_smem);

    // QKV GEMM (bf16) with fused head scatter
    bgemm_k<2><<<dim3(24, 16), 256, bg_smem>>>(wu, WqkvT, 512, 512, 512,
                                               nullptr, rwb, rrb, q1u, q2u, kku, vv);
    // merged r_fw (bx<8) + r_bw reversed (bx>=8) -> rku
    bgemm_k<3><<<dim3(16, 8), 256, bg_smem>>>(ru, WrfwT, 512, 512, 512,
                                              WrbwT, nullptr, nullptr,
                                              rku, rku + 2046 * 512, nullptr, nullptr);
    // V transpose -> bf16x2 [z][d][j/2]
    vt_k<<<dim3(8, 32), 256>>>(vv, vvt);
    // BD band (packed u32 stores)
    bd_k<<<dim3(9, 8, 32), 256>>>(q2u, rku, (unsigned*)bdh);
    // fused AC + BD + mask + softmax + PV -> vec bf16x2
    int fl_smem = (4096 + 4096 + 3 * 2048 + 3 * 2048) * 4 + 1024 * 4;
    cudaFuncSetAttribute(flash_k, cudaFuncAttributeMaxDynamicSharedMemorySize, fl_smem);
    flash_k<<<dim3(8, 32), 256, fl_smem>>>(q1u, kku, vvt, bdh, mask, vecu);
    // attn_out = vec @ W_o (bf16)
    bgemm_k<0><<<dim3(8, 16), 256, bg_smem>>>(vecu, WoT, 512, 512, 512,
                                              nullptr, nullptr, nullptr,
                                              nullptr, nullptr, nullptr, xb);
    // residual + LN
    ln_k<<<2048, 256>>>(w, xb, lng, lnb, out);
}

// round 15
// speedup vs baseline: 1.0511x; 1.0511x over previous
#include <cuda_runtime.h>
#include <cuda_bf16.h>
#include <math.h>

#define SCALE_F 0.125f
#define EPS_F 1e-5f

// ---------------- scratch (device globals) ----------------
__device__ unsigned g_wu[2048 * 512];       // w packed bf16x2 [row][k/2]
__device__ unsigned g_ru[1024 * 512];       // r packed bf16x2
__device__ unsigned g_WqkvT[3072 * 512];    // W_qkv^T bf16x2 [n][k/2]
__device__ unsigned g_WrfwT[1024 * 512];    // W_r_fw^T bf16x2
__device__ unsigned g_WrbwT[1024 * 512];    // W_r_bw^T bf16x2
__device__ unsigned g_WoT[1024 * 512];      // W_o^T bf16x2
__device__ unsigned g_q1u[32 * 1024 * 32];  // q + r_w_bias, bf16x2 [z][i][32]
__device__ unsigned g_q2u[32 * 1024 * 32];  // q + r_r_bias, bf16x2
__device__ unsigned g_kku[32 * 1024 * 32];  // k heads, bf16x2
__device__ float    g_vv[32 * 1024 * 64];   // v heads fp32 [z][i][64]
__device__ unsigned g_vvt[32 * 64 * 512];   // v transposed bf16x2 [z][d][j/2]
__device__ unsigned g_rku[2048 * 512];      // r_k bf16x2 [jr][512] (row 2047 zeroed)
__device__ __nv_bfloat16 g_bdh[67108864];   // BD bf16 [z][1024][2048] (band only)
__device__ unsigned g_vecu[2048 * 512];     // attn vec bf16x2 [(i*2+b)][(n*64+d)/2]
__device__ float    g_x[2048 * 1024];       // vec @ W_o fp32

// ---------------- helpers ----------------
__device__ __forceinline__ void cp16(void* s, const void* g) {
    unsigned a = (unsigned)__cvta_generic_to_shared(s);
    asm volatile("cp.async.cg.shared.global [%0], [%1], 16;\n" ::"r"(a), "l"(g));
}
__device__ __forceinline__ unsigned packbf(float lo, float hi) {
    unsigned u;
    asm("cvt.rn.bf16x2.f32 %0, %1, %2;" : "=r"(u) : "f"(hi), "f"(lo));
    return u;
}
__device__ __forceinline__ int adru(int r, int c) {  // bf16x2 rows of 32 u32, XOR swizzle
    return r * 32 + (((c >> 2) ^ (r & 7)) << 2) + (c & 3);
}
#define MMA_BF16(c, a, b)                                                          \
    asm volatile(                                                                  \
        "mma.sync.aligned.m16n8k16.row.col.f32.bf16.bf16.f32 "                     \
        "{%0,%1,%2,%3},{%4,%5,%6,%7},{%8,%9},{%0,%1,%2,%3};"                       \
        : "+f"(c[0]), "+f"(c[1]), "+f"(c[2]), "+f"(c[3])                           \
        : "r"(a[0]), "r"(a[1]), "r"(a[2]), "r"(a[3]), "r"(b[0]), "r"(b[1]))

// ---------------- merged prep: packs + transposes + zero pad ----------------
__device__ __forceinline__ void packT_body2(const float* in, unsigned* out, int N,
                                            int n0, int k0, float (*ts)[65]) {
    int t = threadIdx.x;
#pragma unroll
    for (int e = 0; e < 16; e++) {
        int idx = e * 256 + t, kk = idx >> 6, nn = idx & 63;
        ts[kk][nn] = in[(long long)(k0 + kk) * N + n0 + nn];
    }
    __syncthreads();
#pragma unroll
    for (int e = 0; e < 8; e++) {
        int idx = e * 256 + t, nn = idx >> 5, kp = idx & 31;
        out[(long long)(n0 + nn) * 512 + (k0 >> 1) + kp] =
            packbf(ts[2 * kp][nn], ts[2 * kp + 1][nn]);
    }
}
__global__ __launch_bounds__(256) void prep_k(
    const float* __restrict__ w, unsigned* __restrict__ wu,
    const float* __restrict__ r, unsigned* __restrict__ ru,
    const float* __restrict__ Wqkv, unsigned* __restrict__ WqkvT,
    const float* __restrict__ Wrfw, unsigned* __restrict__ WrfwT,
    const float* __restrict__ Wrbw, unsigned* __restrict__ WrbwT,
    const float* __restrict__ Wo, unsigned* __restrict__ WoT,
    unsigned* __restrict__ rkpad) {
    __shared__ float ts[64][65];
    int b = blockIdx.x;
    if (b < 4096) {
        int i = b * 256 + threadIdx.x;
        float2 v = ((const float2*)w)[i];
        wu[i] = packbf(v.x, v.y);
    } else if (b < 6144) {
        int i = (b - 4096) * 256 + threadIdx.x;
        float2 v = ((const float2*)r)[i];
        ru[i] = packbf(v.x, v.y);
    } else if (b < 6912) {
        int idx = b - 6144;
        packT_body2(Wqkv, WqkvT, 3072, (idx % 48) * 64, (idx / 48) * 64, ts);
    } else if (b < 7680) {
        int idx = b - 6912;
        int zsel = idx >> 8; idx &= 255;
        const float* in = (zsel == 0) ? Wrfw : (zsel == 1) ? Wrbw : Wo;
        unsigned* outp = (zsel == 0) ? WrfwT : (zsel == 1) ? WrbwT : WoT;
        packT_body2(in, outp, 1024, (idx & 15) * 64, (idx >> 4) * 64, ts);
    } else {
        rkpad[(b - 7680) * 256 + threadIdx.x] = 0u;
    }
}

// ---------------- merged QKV + rk GEMM (bf16 128x128, K=1024) ----------------
// bid < 384: QKV (head-scatter epilogue). bid >= 384: rk fw/bw epilogue.
__global__ __launch_bounds__(256, 2) void gemms_k(
    const unsigned* __restrict__ Aq, const unsigned* __restrict__ Bq,
    const float* __restrict__ bias1, const float* __restrict__ bias2,
    unsigned* __restrict__ u1, unsigned* __restrict__ u2, unsigned* __restrict__ u3,
    float* __restrict__ f4,
    const unsigned* __restrict__ Ar, const unsigned* __restrict__ Bfw,
    const unsigned* __restrict__ Bbw,
    unsigned* __restrict__ rkf, unsigned* __restrict__ rkb) {
    extern __shared__ unsigned su[];
    int t = threadIdx.x, lane = t & 31, lq = lane & 3, lr = lane >> 2;
    int bid = blockIdx.x;
    bool qkv = bid < 384;
    const unsigned* A;
    const unsigned* B;
    int row0, col0;
    bool bw = false;
    if (qkv) {
        A = Aq; B = Bq;
        col0 = (bid % 24) * 128;
        row0 = (bid / 24) * 128;
    } else {
        int idx = bid - 384;
        int bx = idx & 15;
        row0 = (idx >> 4) * 128;
        col0 = (bx & 7) * 128;
        bw = bx >= 8;
        A = Ar; B = bw ? Bbw : Bfw;
    }
    int warp = t >> 5, wm = warp >> 1, wn = warp & 1;

    float acc[2][8][4] = {};

    auto load_tile = [&](int kt, int st) {
        unsigned* sA = su + st * 8192;
        unsigned* sB = sA + 4096;
        int k0 = kt * 32;
#pragma unroll
        for (int e = 0; e < 4; e++) {
            int c = e * 256 + t, r = c >> 3, c4 = c & 7;
            cp16(sA + r * 32 + ((c4 ^ (r & 7)) << 2),
                 A + (long long)(row0 + r) * 512 + k0 + c4 * 4);
            cp16(sB + r * 32 + ((c4 ^ (r & 7)) << 2),
                 B + (long long)(col0 + r) * 512 + k0 + c4 * 4);
        }
        asm volatile("cp.async.commit_group;\n");
    };

    load_tile(0, 0);
    for (int kt = 0; kt < 16; kt++) {
        int st = kt & 1;
        if (kt + 1 < 16) {
            load_tile(kt + 1, st ^ 1);
            asm volatile("cp.async.wait_group 1;\n");
        } else {
            asm volatile("cp.async.wait_group 0;\n");
        }
        __syncthreads();
        unsigned* sA = su + st * 8192;
        unsigned* sB = sA + 4096;
#pragma unroll
        for (int s = 0; s < 4; s++) {
            unsigned af[2][4], bf[8][2];
#pragma unroll
            for (int mt = 0; mt < 2; mt++) {
                int r = wm * 32 + mt * 16 + lr;
                af[mt][0] = sA[adru(r, s * 8 + lq)];
                af[mt][1] = sA[adru(r + 8, s * 8 + lq)];
                af[mt][2] = sA[adru(r, s * 8 + 4 + lq)];
                af[mt][3] = sA[adru(r + 8, s * 8 + 4 + lq)];
            }
#pragma unroll
            for (int nt = 0; nt < 8; nt++) {
                int nn = wn * 64 + nt * 8 + lr;
                bf[nt][0] = sB[adru(nn, s * 8 + lq)];
                bf[nt][1] = sB[adru(nn, s * 8 + 4 + lq)];
            }
#pragma unroll
            for (int mt = 0; mt < 2; mt++)
#pragma unroll
                for (int nt = 0; nt < 8; nt++) MMA_BF16(acc[mt][nt], af[mt], bf[nt]);
        }
        __syncthreads();
    }

#pragma unroll
    for (int mt = 0; mt < 2; mt++)
#pragma unroll
        for (int nt = 0; nt < 8; nt++) {
            int r0 = row0 + wm * 32 + mt * 16 + lr;
            int cb = col0 + wn * 64 + nt * 8 + 2 * lq;
#pragma unroll
            for (int pe = 0; pe < 2; pe++) {
                int rr = r0 + pe * 8;
                float v0 = acc[mt][nt][pe * 2], v1 = acc[mt][nt][pe * 2 + 1];
                if (qkv) {
                    int i = rr >> 1, bb = rr & 1;
                    int sec = cb >> 10, c1 = cb & 1023, n = c1 >> 6, d = c1 & 63;
                    int z = bb * 16 + n;
                    if (sec == 0) {
                        long long idx = ((long long)z << 15) + (i << 5) + (d >> 1);
                        u1[idx] = packbf(v0 + bias1[c1], v1 + bias1[c1 + 1]);
                        u2[idx] = packbf(v0 + bias2[c1], v1 + bias2[c1 + 1]);
                    } else if (sec == 1) {
                        u3[((long long)z << 15) + (i << 5) + (d >> 1)] = packbf(v0, v1);
                    } else {
                        long long idx = ((long long)z << 16) + (i << 6) + d;
                        f4[idx] = v0; f4[idx + 1] = v1;
                    }
                } else {
                    if (bw) {
                        if (rr == 1023) continue;  // fw owns rk row 1023
                        rkb[(long long)rr * (-512) + (cb >> 1)] = packbf(v0, v1);
                    } else {
                        rkf[(long long)rr * 512 + (cb >> 1)] = packbf(v0, v1);
                    }
                }
            }
        }
}

// ---------------- merged V-transpose + BD band GEMM ----------------
// bid < 2304: bd tile. bid >= 2304: vt tile.
__global__ __launch_bounds__(256, 2) void vtbd_k(
    const unsigned* __restrict__ q2, const unsigned* __restrict__ rk,
    unsigned* __restrict__ bdu,
    const float* __restrict__ vv, unsigned* __restrict__ vvt) {
    extern __shared__ unsigned dsm[];
    int t = threadIdx.x, bid = blockIdx.x;
    if (bid < 2304) {
        // ---- BD band GEMM ----
        unsigned* sA = dsm;
        unsigned* sB = dsm + 4096;
        int lane = t & 31, lq = lane & 3, lr = lane >> 2;
        int z = bid / 72, rem = bid % 72;
        int row0 = (rem / 9) * 128;
        int col0 = 896 - row0 + (rem % 9) * 128;
        const unsigned* Az = q2 + ((long long)z << 15);
        const unsigned* Bz = rk + (long long)(z & 15) * 32;
        unsigned* Cz = bdu + ((long long)z << 20);
        int warp = t >> 5, wm = warp >> 1, wn = warp & 1;

#pragma unroll
        for (int e = 0; e < 4; e++) {
            int c = e * 256 + t, r = c >> 3, c4 = c & 7;
            cp16(sA + r * 32 + ((c4 ^ (r & 7)) << 2), Az + (long long)(row0 + r) * 32 + c4 * 4);
            cp16(sB + r * 32 + ((c4 ^ (r & 7)) << 2), Bz + (long long)(col0 + r) * 512 + c4 * 4);
        }
        asm volatile("cp.async.commit_group;\ncp.async.wait_group 0;\n");
        __syncthreads();

        float acc[2][8][4] = {};
#pragma unroll
        for (int s = 0; s < 4; s++) {
            unsigned af[2][4], bf[8][2];
#pragma unroll
            for (int mt = 0; mt < 2; mt++) {
                int r = wm * 32 + mt * 16 + lr;
                af[mt][0] = sA[adru(r, s * 8 + lq)];
                af[mt][1] = sA[adru(r + 8, s * 8 + lq)];
                af[mt][2] = sA[adru(r, s * 8 + 4 + lq)];
                af[mt][3] = sA[adru(r + 8, s * 8 + 4 + lq)];
            }
#pragma unroll
            for (int nt = 0; nt < 8; nt++) {
                int nn = wn * 64 + nt * 8 + lr;
                bf[nt][0] = sB[adru(nn, s * 8 + lq)];
                bf[nt][1] = sB[adru(nn, s * 8 + 4 + lq)];
            }
#pragma unroll
            for (int mt = 0; mt < 2; mt++)
#pragma unroll
                for (int nt = 0; nt < 8; nt++) MMA_BF16(acc[mt][nt], af[mt], bf[nt]);
        }

#pragma unroll
        for (int mt = 0; mt < 2; mt++)
#pragma unroll
            for (int nt = 0; nt < 8; nt++) {
                int r0 = row0 + wm * 32 + mt * 16 + lr;
                int cb = col0 + wn * 64 + nt * 8 + 2 * lq;
#pragma unroll
                for (int pe = 0; pe < 2; pe++) {
                    int rr = r0 + pe * 8;
                    Cz[((rr << 11) + cb) >> 1] =
                        packbf(acc[mt][nt][pe * 2], acc[mt][nt][pe * 2 + 1]);
                }
            }
    } else {
        // ---- V transpose ----
        float (*ts)[65] = (float(*)[65])dsm;
        int idx = bid - 2304;
        int z = idx >> 3, j0 = (idx & 7) * 128;
        const float* Vz = vv + ((long long)z << 16);
#pragma unroll
        for (int e = 0; e < 8; e++) {
            int c = e * 256 + t, r = c >> 4, c4 = c & 15;
            float4 v = *(const float4*)(Vz + (long long)(j0 + r) * 64 + c4 * 4);
            ts[r][c4 * 4] = v.x; ts[r][c4 * 4 + 1] = v.y;
            ts[r][c4 * 4 + 2] = v.z; ts[r][c4 * 4 + 3] = v.w;
        }
        __syncthreads();
#pragma unroll
        for (int e = 0; e < 16; e++) {
            int c = e * 256 + t, d = c >> 6, jp = c & 63;
            vvt[((long long)z << 15) + (d << 9) + (j0 >> 1) + jp] =
                packbf(ts[jp * 2][d], ts[jp * 2 + 1][d]);
        }
    }
}

// ---------------- bf16 GEMM 128x128 — Wo (fp32 store) ----------------
__global__ __launch_bounds__(256, 2) void wo_k(
    const unsigned* __restrict__ A, const unsigned* __restrict__ B,
    float* __restrict__ f4) {
    extern __shared__ unsigned su[];
    int t = threadIdx.x, lane = t & 31, lq = lane & 3, lr = lane >> 2;
    int row0 = blockIdx.y * 128, col0 = blockIdx.x * 128;
    int warp = t >> 5, wm = warp >> 1, wn = warp & 1;

    float acc[2][8][4] = {};

    auto load_tile = [&](int kt, int st) {
        unsigned* sA = su + st * 8192;
        unsigned* sB = sA + 4096;
        int k0 = kt * 32;
#pragma unroll
        for (int e = 0; e < 4; e++) {
            int c = e * 256 + t, r = c >> 3, c4 = c & 7;
            cp16(sA + r * 32 + ((c4 ^ (r & 7)) << 2),
                 A + (long long)(row0 + r) * 512 + k0 + c4 * 4);
            cp16(sB + r * 32 + ((c4 ^ (r & 7)) << 2),
                 B + (long long)(col0 + r) * 512 + k0 + c4 * 4);
        }
        asm volatile("cp.async.commit_group;\n");
    };

    load_tile(0, 0);
    for (int kt = 0; kt < 16; kt++) {
        int st = kt & 1;
        if (kt + 1 < 16) {
            load_tile(kt + 1, st ^ 1);
            asm volatile("cp.async.wait_group 1;\n");
        } else {
            asm volatile("cp.async.wait_group 0;\n");
        }
        __syncthreads();
        unsigned* sA = su + st * 8192;
        unsigned* sB = sA + 4096;
#pragma unroll
        for (int s = 0; s < 4; s++) {
            unsigned af[2][4], bf[8][2];
#pragma unroll
            for (int mt = 0; mt < 2; mt++) {
                int r = wm * 32 + mt * 16 + lr;
                af[mt][0] = sA[adru(r, s * 8 + lq)];
                af[mt][1] = sA[adru(r + 8, s * 8 + lq)];
                af[mt][2] = sA[adru(r, s * 8 + 4 + lq)];
                af[mt][3] = sA[adru(r + 8, s * 8 + 4 + lq)];
            }
#pragma unroll
            for (int nt = 0; nt < 8; nt++) {
                int nn = wn * 64 + nt * 8 + lr;
                bf[nt][0] = sB[adru(nn, s * 8 + lq)];
                bf[nt][1] = sB[adru(nn, s * 8 + 4 + lq)];
            }
#pragma unroll
            for (int mt = 0; mt < 2; mt++)
#pragma unroll
                for (int nt = 0; nt < 8; nt++) MMA_BF16(acc[mt][nt], af[mt], bf[nt]);
        }
        __syncthreads();
    }

#pragma unroll
    for (int mt = 0; mt < 2; mt++)
#pragma unroll
        for (int nt = 0; nt < 8; nt++) {
            int r0 = row0 + wm * 32 + mt * 16 + lr;
            int cb = col0 + wn * 64 + nt * 8 + 2 * lq;
#pragma unroll
            for (int pe = 0; pe < 2; pe++) {
                int rr = r0 + pe * 8;
                f4[(long long)rr * 1024 + cb] = acc[mt][nt][pe * 2];
                f4[(long long)rr * 1024 + cb + 1] = acc[mt][nt][pe * 2 + 1];
            }
        }
}

// ---------------- flash (bf16): S = Q1·K^T + BD_band, mask, online softmax, P·V ----------------
__global__ __launch_bounds__(256, 2) void flash_k(
    const unsigned* __restrict__ q1, const unsigned* __restrict__ kk,
    const unsigned* __restrict__ vvt, const __nv_bfloat16* __restrict__ bdh,
    const unsigned char* __restrict__ mask, unsigned* __restrict__ vecu) {
    extern __shared__ unsigned fsu[];
    unsigned* sQ = fsu;
    unsigned* sP = sQ + 4096;
    unsigned* sK = sP + 4096;
    unsigned* sVt = sK + 3 * 2048;
    float* sMask = (float*)(sVt + 3 * 2048);

    int t = threadIdx.x, lane = t & 31, warp = t >> 5;
    int lq = lane & 3, lr = lane >> 2;
    int i0 = blockIdx.x * 128, z = blockIdx.y, b = z >> 4, nh = z & 15;
    const unsigned* Qz = q1 + ((long long)z << 15);
    const unsigned* Kz = kk + ((long long)z << 15);
    const unsigned* Vtz = vvt + ((long long)z << 15);
    const __nv_bfloat16* bdz = bdh + ((long long)z << 21);

    for (int e = t; e < 1024; e += 256) sMask[e] = mask[e * 2 + b] ? 1.0f : 0.0f;

#pragma unroll
    for (int e = 0; e < 4; e++) {
        int c = e * 256 + t, r = c >> 3, c4 = c & 7;
        cp16(sQ + r * 32 + ((c4 ^ (r & 7)) << 2), Qz + (long long)(i0 + r) * 32 + c4 * 4);
    }
    auto loadKV = [&](int jt, int bufi) {
        unsigned* dK = sK + bufi * 2048;
        unsigned* dV = sVt + bufi * 2048;
        int j0 = jt * 64;
#pragma unroll
        for (int e = 0; e < 2; e++) {
            int c = e * 256 + t, r = c >> 3, c4 = c & 7;
            cp16(dK + r * 32 + ((c4 ^ (r & 7)) << 2), Kz + (long long)(j0 + r) * 32 + c4 * 4);
            cp16(dV + r * 32 + ((c4 ^ (r & 7)) << 2),
                 Vtz + ((long long)r << 9) + (j0 >> 1) + c4 * 4);
        }
        asm volatile("cp.async.commit_group;\n");
    };
    loadKV(0, 0);
    loadKV(1, 1);

    float mA = -3.4e38f, mB = -3.4e38f, lA = 0.f, lB = 0.f;
    float O[8][4] = {};
    int rb = warp * 16 + lr;
    int rowA = i0 + rb;
    const unsigned short* bd0 = (const unsigned short*)(bdz + (long long)rowA * 2048 + (1023 - rowA));
    const unsigned short* bd1 = (const unsigned short*)(bdz + (long long)(rowA + 8) * 2048 + (1015 - rowA));

    unsigned pbv[16];
    auto prefetchBD = [&](int jt) {
#pragma unroll
        for (int nt = 0; nt < 8; nt++) {
            int jc = jt * 64 + nt * 8 + 2 * lq;
            unsigned short l0 = __ldg(bd0 + jc), h0 = __ldg(bd0 + jc + 1);
            unsigned short l1 = __ldg(bd1 + jc), h1 = __ldg(bd1 + jc + 1);
            pbv[2 * nt] = (unsigned)l0 | ((unsigned)h0 << 16);
            pbv[2 * nt + 1] = (unsigned)l1 | ((unsigned)h1 << 16);
        }
    };
    prefetchBD(0);

    for (int jt = 0; jt < 16; jt++) {
        int buf = jt % 3;
        if (jt == 15) asm volatile("cp.async.wait_group 0;\n");
        else          asm volatile("cp.async.wait_group 1;\n");
        __syncthreads();

        unsigned* cK = sK + buf * 2048;
        float S[8][4] = {};
#pragma unroll
        for (int s = 0; s < 4; s++) {
            unsigned a[4];
            a[0] = sQ[adru(rb, s * 8 + lq)];
            a[1] = sQ[adru(rb + 8, s * 8 + lq)];
            a[2] = sQ[adru(rb, s * 8 + 4 + lq)];
            a[3] = sQ[adru(rb + 8, s * 8 + 4 + lq)];
#pragma unroll
            for (int nt = 0; nt < 8; nt++) {
                int nn = nt * 8 + lr;
                unsigned bfx[2];
                bfx[0] = cK[adru(nn, s * 8 + lq)];
                bfx[1] = cK[adru(nn, s * 8 + 4 + lq)];
                MMA_BF16(S[nt], a, bfx);
            }
        }

        int j0 = jt * 64;
#pragma unroll
        for (int nt = 0; nt < 8; nt++) {
            int jc = j0 + nt * 8 + 2 * lq;
            float2 f0 = __bfloat1622float2(*reinterpret_cast<__nv_bfloat162*>(&pbv[2 * nt]));
            float2 f1 = __bfloat1622float2(*reinterpret_cast<__nv_bfloat162*>(&pbv[2 * nt + 1]));
            float s0 = (S[nt][0] + f0.x) * SCALE_F;
            float s1 = (S[nt][1] + f0.y) * SCALE_F;
            float s2 = (S[nt][2] + f1.x) * SCALE_F;
            float s3 = (S[nt][3] + f1.y) * SCALE_F;
            if (sMask[jc] != 0.f)     { s0 = -1e30f; s2 = -1e30f; }
            if (sMask[jc + 1] != 0.f) { s1 = -1e30f; s3 = -1e30f; }
            S[nt][0] = s0; S[nt][1] = s1; S[nt][2] = s2; S[nt][3] = s3;
        }

        float mxA = -3.4e38f, mxB = -3.4e38f;
#pragma unroll
        for (int nt = 0; nt < 8; nt++) {
            mxA = fmaxf(mxA, fmaxf(S[nt][0], S[nt][1]));
            mxB = fmaxf(mxB, fmaxf(S[nt][2], S[nt][3]));
        }
        mxA = fmaxf(mxA, __shfl_xor_sync(0xffffffffu, mxA, 1));
        mxA = fmaxf(mxA, __shfl_xor_sync(0xffffffffu, mxA, 2));
        mxB = fmaxf(mxB, __shfl_xor_sync(0xffffffffu, mxB, 1));
        mxB = fmaxf(mxB, __shfl_xor_sync(0xffffffffu, mxB, 2));
        float nmA = fmaxf(mA, mxA), nmB = fmaxf(mB, mxB);
        float scA = __expf(mA - nmA), scB = __expf(mB - nmB);
        mA = nmA; mB = nmB;
        float smA = 0.f, smB = 0.f;
#pragma unroll
        for (int nt = 0; nt < 8; nt++) {
            float p0 = __expf(S[nt][0] - nmA), p1 = __expf(S[nt][1] - nmA);
            float p2 = __expf(S[nt][2] - nmB), p3 = __expf(S[nt][3] - nmB);
            smA += p0 + p1; smB += p2 + p3;
            sP[adru(rb, nt * 4 + lq)] = packbf(p0, p1);
            sP[adru(rb + 8, nt * 4 + lq)] = packbf(p2, p3);
        }
        smA += __shfl_xor_sync(0xffffffffu, smA, 1);
        smA += __shfl_xor_sync(0xffffffffu, smA, 2);
        smB += __shfl_xor_sync(0xffffffffu, smB, 1);
        smB += __shfl_xor_sync(0xffffffffu, smB, 2);
        lA = lA * scA + smA;
        lB = lB * scB + smB;
#pragma unroll
        for (int nt = 0; nt < 8; nt++) {
            O[nt][0] *= scA; O[nt][1] *= scA;
            O[nt][2] *= scB; O[nt][3] *= scB;
        }
        __syncwarp();

        unsigned* cV = sVt + buf * 2048;
#pragma unroll
        for (int s = 0; s < 4; s++) {
            unsigned a[4];
            a[0] = sP[adru(rb, s * 8 + lq)];
            a[1] = sP[adru(rb + 8, s * 8 + lq)];
            a[2] = sP[adru(rb, s * 8 + 4 + lq)];
            a[3] = sP[adru(rb + 8, s * 8 + 4 + lq)];
#pragma unroll
            for (int nt = 0; nt < 8; nt++) {
                int nn = nt * 8 + lr;
                unsigned bfx[2];
                bfx[0] = cV[adru(nn, s * 8 + lq)];
                bfx[1] = cV[adru(nn, s * 8 + 4 + lq)];
                MMA_BF16(O[nt], a, bfx);
            }
        }

        if (jt + 2 < 16) loadKV(jt + 2, (jt + 2) % 3);
        if (jt + 1 < 16) prefetchBD(jt + 1);
    }

    float iA = 1.0f / lA, iB = 1.0f / lB;
#pragma unroll
    for (int nt = 0; nt < 8; nt++) {
        int cp = (nh << 5) + nt * 4 + lq;
        vecu[(((long long)(rowA * 2 + b)) << 9) + cp] = packbf(O[nt][0] * iA, O[nt][1] * iA);
        vecu[(((long long)((rowA + 8) * 2 + b)) << 9) + cp] = packbf(O[nt][2] * iB, O[nt][3] * iB);
    }
}

// ---------------- residual + LayerNorm (float4) ----------------
__global__ void ln_k(const float* __restrict__ w, const float* __restrict__ xb,
                     const float* __restrict__ g, const float* __restrict__ bb,
                     float* __restrict__ out) {
    __shared__ float smr[16];
    int row = blockIdx.x, t = threadIdx.x;
    const float4* wr = (const float4*)(w + (long long)row * 1024);
    const float4* xr = (const float4*)(xb + (long long)row * 1024);
    float4 wv = wr[t], xv = xr[t];
    float l0 = wv.x + xv.x, l1 = wv.y + xv.y, l2 = wv.z + xv.z, l3 = wv.w + xv.w;
    float s = l0 + l1 + l2 + l3;
    float sq = l0 * l0 + l1 * l1 + l2 * l2 + l3 * l3;
#pragma unroll
    for (int o = 16; o; o >>= 1) {
        s += __shfl_xor_sync(0xffffffffu, s, o);
        sq += __shfl_xor_sync(0xffffffffu, sq, o);
    }
    if ((t & 31) == 0) { smr[t >> 5] = s; smr[8 + (t >> 5)] = sq; }
    __syncthreads();
    s = smr[t & 7]; sq = smr[8 + (t & 7)];
#pragma unroll
    for (int o = 4; o; o >>= 1) {
        s += __shfl_xor_sync(0xffffffffu, s, o);
        sq += __shfl_xor_sync(0xffffffffu, sq, o);
    }
    float mu = s * (1.0f / 1024.0f);
    float var = sq * (1.0f / 1024.0f) - mu * mu;
    float rstd = rsqrtf(var + EPS_F);
    float4 gv = ((const float4*)g)[t];
    float4 bv = ((const float4*)bb)[t];
    float4 ov;
    ov.x = (l0 - mu) * rstd * gv.x + bv.x;
    ov.y = (l1 - mu) * rstd * gv.y + bv.y;
    ov.z = (l2 - mu) * rstd * gv.z + bv.z;
    ov.w = (l3 - mu) * rstd * gv.w + bv.w;
    ((float4*)(out + (long long)row * 1024))[t] = ov;
}

// ---------------- launch ----------------
extern "C" void kernel_launch(void* const* d_in, const int* in_sizes, int n_in,
                              void* d_out, int out_size) {
    const float* w    = (const float*)d_in[0];
    const float* r    = (const float*)d_in[1];
    const float* rwb  = (const float*)d_in[2];
    const float* rrb  = (const float*)d_in[3];
    const unsigned char* mask = (const unsigned char*)d_in[4];
    const float* Wqkv = (const float*)d_in[5];
    const float* Wrfw = (const float*)d_in[6];
    const float* Wrbw = (const float*)d_in[7];
    const float* Wo   = (const float*)d_in[8];
    const float* lng  = (const float*)d_in[9];
    const float* lnb  = (const float*)d_in[10];
    float* out = (float*)d_out;

    unsigned *wu, *ru, *WqkvT, *WrfwT, *WrbwT, *WoT;
    unsigned *q1u, *q2u, *kku, *rku, *vvt, *vecu;
    __nv_bfloat16* bdh;
    float *vv, *xb;
    cudaGetSymbolAddress((void**)&wu, g_wu);
    cudaGetSymbolAddress((void**)&ru, g_ru);
    cudaGetSymbolAddress((void**)&WqkvT, g_WqkvT);
    cudaGetSymbolAddress((void**)&WrfwT, g_WrfwT);
    cudaGetSymbolAddress((void**)&WrbwT, g_WrbwT);
    cudaGetSymbolAddress((void**)&WoT, g_WoT);
    cudaGetSymbolAddress((void**)&q1u, g_q1u);
    cudaGetSymbolAddress((void**)&q2u, g_q2u);
    cudaGetSymbolAddress((void**)&kku, g_kku);
    cudaGetSymbolAddress((void**)&vv, g_vv);
    cudaGetSymbolAddress((void**)&vvt, g_vvt);
    cudaGetSymbolAddress((void**)&rku, g_rku);
    cudaGetSymbolAddress((void**)&bdh, g_bdh);
    cudaGetSymbolAddress((void**)&vecu, g_vecu);
    cudaGetSymbolAddress((void**)&xb, g_x);

    prep_k<<<7682, 256>>>(w, wu, r, ru, Wqkv, WqkvT, Wrfw, WrfwT,
                          Wrbw, WrbwT, Wo, WoT, rku + 2047 * 512);

    int bg_smem = 2 * 8192 * 4;  // 64 KB
    cudaFuncSetAttribute(gemms_k, cudaFuncAttributeMaxDynamicSharedMemorySize, bg_smem);
    cudaFuncSetAttribute(wo_k, cudaFuncAttributeMaxDynamicSharedMemorySize, bg_smem);

    // merged QKV (384 blocks) + rk fw/bw (128 blocks)
    gemms_k<<<512, 256, bg_smem>>>(wu, WqkvT, rwb, rrb, q1u, q2u, kku, vv,
                                   ru, WrfwT, WrbwT, rku, rku + 2046 * 512);

    // merged BD band (2304 blocks) + V transpose (256 blocks)
    int vb_smem = 130 * 256 + 1024;  // max(bd 32KB, vt 33280B) rounded up
    cudaFuncSetAttribute(vtbd_k, cudaFuncAttributeMaxDynamicSharedMemorySize, vb_smem);
    vtbd_k<<<2560, 256, vb_smem>>>(q2u, rku, (unsigned*)bdh, vv, vvt);

    // fused AC + BD + mask + softmax + PV -> vec bf16x2
    int fl_smem = (4096 + 4096 + 3 * 2048 + 3 * 2048) * 4 + 1024 * 4;
    cudaFuncSetAttribute(flash_k, cudaFuncAttributeMaxDynamicSharedMemorySize, fl_smem);
    flash_k<<<dim3(8, 32), 256, fl_smem>>>(q1u, kku, vvt, bdh, mask, vecu);

    // attn_out = vec @ W_o (bf16)
    wo_k<<<dim3(8, 16), 256, bg_smem>>>(vecu, WoT, xb);

    // residual + LN
    ln_k<<<2048, 256>>>(w, xb, lng, lnb, out);
}

// round 16
// speedup vs baseline: 1.0875x; 1.0346x over previous
#include <cuda_runtime.h>
#include <cuda_bf16.h>
#include <math.h>

#define SCALE_F 0.125f
#define EPS_F 1e-5f

// ---------------- scratch (device globals) ----------------
__device__ unsigned g_wu[2048 * 512];       // w packed bf16x2 [row][k/2]
__device__ unsigned g_ru[1024 * 512];       // r packed bf16x2
__device__ unsigned g_WqkvT[3072 * 512];    // W_qkv^T bf16x2 [n][k/2]
__device__ unsigned g_WrfwT[1024 * 512];    // W_r_fw^T bf16x2
__device__ unsigned g_WrbwT[1024 * 512];    // W_r_bw^T bf16x2
__device__ unsigned g_WoT[1024 * 512];      // W_o^T bf16x2
__device__ unsigned g_q1u[32 * 1024 * 32];  // q + r_w_bias, bf16x2 [z][i][32]
__device__ unsigned g_q2u[32 * 1024 * 32];  // q + r_r_bias, bf16x2
__device__ unsigned g_kku[32 * 1024 * 32];  // k heads, bf16x2
__device__ float    g_vv[32 * 1024 * 64];   // v heads fp32 [z][i][64]
__device__ unsigned g_vvt[32 * 64 * 512];   // v transposed bf16x2 [z][d][j/2]
__device__ unsigned g_rku[2048 * 512];      // r_k bf16x2 [jr][512] (row 2047 zeroed)
__device__ __nv_bfloat16 g_bdh[67108864];   // BD bf16 band; masked cells = -1e38
__device__ unsigned g_vecu[2048 * 512];     // attn vec bf16x2 [(i*2+b)][(n*64+d)/2]
__device__ float    g_x[2048 * 1024];       // vec @ W_o fp32

// ---------------- helpers ----------------
__device__ __forceinline__ void cp16(void* s, const void* g) {
    unsigned a = (unsigned)__cvta_generic_to_shared(s);
    asm volatile("cp.async.cg.shared.global [%0], [%1], 16;\n" ::"r"(a), "l"(g));
}
__device__ __forceinline__ unsigned packbf(float lo, float hi) {
    unsigned u;
    asm("cvt.rn.bf16x2.f32 %0, %1, %2;" : "=r"(u) : "f"(hi), "f"(lo));
    return u;
}
__device__ __forceinline__ int adru(int r, int c) {  // bf16x2 rows of 32 u32, XOR swizzle
    return r * 32 + (((c >> 2) ^ (r & 7)) << 2) + (c & 3);
}
#define MMA_BF16(c, a, b)                                                          \
    asm volatile(                                                                  \
        "mma.sync.aligned.m16n8k16.row.col.f32.bf16.bf16.f32 "                     \
        "{%0,%1,%2,%3},{%4,%5,%6,%7},{%8,%9},{%0,%1,%2,%3};"                       \
        : "+f"(c[0]), "+f"(c[1]), "+f"(c[2]), "+f"(c[3])                           \
        : "r"(a[0]), "r"(a[1]), "r"(a[2]), "r"(a[3]), "r"(b[0]), "r"(b[1]))

// ---------------- merged prep: packs + transposes + zero pad ----------------
__device__ __forceinline__ void packT_body2(const float* in, unsigned* out, int N,
                                            int n0, int k0, float (*ts)[65]) {
    int t = threadIdx.x;
#pragma unroll
    for (int e = 0; e < 16; e++) {
        int idx = e * 256 + t, kk = idx >> 6, nn = idx & 63;
        ts[kk][nn] = in[(long long)(k0 + kk) * N + n0 + nn];
    }
    __syncthreads();
#pragma unroll
    for (int e = 0; e < 8; e++) {
        int idx = e * 256 + t, nn = idx >> 5, kp = idx & 31;
        out[(long long)(n0 + nn) * 512 + (k0 >> 1) + kp] =
            packbf(ts[2 * kp][nn], ts[2 * kp + 1][nn]);
    }
}
__global__ __launch_bounds__(256) void prep_k(
    const float* __restrict__ w, unsigned* __restrict__ wu,
    const float* __restrict__ r, unsigned* __restrict__ ru,
    const float* __restrict__ Wqkv, unsigned* __restrict__ WqkvT,
    const float* __restrict__ Wrfw, unsigned* __restrict__ WrfwT,
    const float* __restrict__ Wrbw, unsigned* __restrict__ WrbwT,
    const float* __restrict__ Wo, unsigned* __restrict__ WoT,
    unsigned* __restrict__ rkpad) {
    __shared__ float ts[64][65];
    int b = blockIdx.x;
    if (b < 4096) {
        int i = b * 256 + threadIdx.x;
        float2 v = ((const float2*)w)[i];
        wu[i] = packbf(v.x, v.y);
    } else if (b < 6144) {
        int i = (b - 4096) * 256 + threadIdx.x;
        float2 v = ((const float2*)r)[i];
        ru[i] = packbf(v.x, v.y);
    } else if (b < 6912) {
        int idx = b - 6144;
        packT_body2(Wqkv, WqkvT, 3072, (idx % 48) * 64, (idx / 48) * 64, ts);
    } else if (b < 7680) {
        int idx = b - 6912;
        int zsel = idx >> 8; idx &= 255;
        const float* in = (zsel == 0) ? Wrfw : (zsel == 1) ? Wrbw : Wo;
        unsigned* outp = (zsel == 0) ? WrfwT : (zsel == 1) ? WrbwT : WoT;
        packT_body2(in, outp, 1024, (idx & 15) * 64, (idx >> 4) * 64, ts);
    } else {
        rkpad[(b - 7680) * 256 + threadIdx.x] = 0u;
    }
}

// ---------------- merged QKV + rk GEMM (bf16 128x128, K=1024) ----------------
__global__ __launch_bounds__(256, 2) void gemms_k(
    const unsigned* __restrict__ Aq, const unsigned* __restrict__ Bq,
    const float* __restrict__ bias1, const float* __restrict__ bias2,
    unsigned* __restrict__ u1, unsigned* __restrict__ u2, unsigned* __restrict__ u3,
    float* __restrict__ f4,
    const unsigned* __restrict__ Ar, const unsigned* __restrict__ Bfw,
    const unsigned* __restrict__ Bbw,
    unsigned* __restrict__ rkf, unsigned* __restrict__ rkb) {
    extern __shared__ unsigned su[];
    int t = threadIdx.x, lane = t & 31, lq = lane & 3, lr = lane >> 2;
    int bid = blockIdx.x;
    bool qkv = bid < 384;
    const unsigned* A;
    const unsigned* B;
    int row0, col0;
    bool bw = false;
    if (qkv) {
        A = Aq; B = Bq;
        col0 = (bid % 24) * 128;
        row0 = (bid / 24) * 128;
    } else {
        int idx = bid - 384;
        int bx = idx & 15;
        row0 = (idx >> 4) * 128;
        col0 = (bx & 7) * 128;
        bw = bx >= 8;
        A = Ar; B = bw ? Bbw : Bfw;
    }
    int warp = t >> 5, wm = warp >> 1, wn = warp & 1;

    float acc[2][8][4] = {};

    auto load_tile = [&](int kt, int st) {
        unsigned* sA = su + st * 8192;
        unsigned* sB = sA + 4096;
        int k0 = kt * 32;
#pragma unroll
        for (int e = 0; e < 4; e++) {
            int c = e * 256 + t, r = c >> 3, c4 = c & 7;
            cp16(sA + r * 32 + ((c4 ^ (r & 7)) << 2),
                 A + (long long)(row0 + r) * 512 + k0 + c4 * 4);
            cp16(sB + r * 32 + ((c4 ^ (r & 7)) << 2),
                 B + (long long)(col0 + r) * 512 + k0 + c4 * 4);
        }
        asm volatile("cp.async.commit_group;\n");
    };

    load_tile(0, 0);
    for (int kt = 0; kt < 16; kt++) {
        int st = kt & 1;
        if (kt + 1 < 16) {
            load_tile(kt + 1, st ^ 1);
            asm volatile("cp.async.wait_group 1;\n");
        } else {
            asm volatile("cp.async.wait_group 0;\n");
        }
        __syncthreads();
        unsigned* sA = su + st * 8192;
        unsigned* sB = sA + 4096;
#pragma unroll
        for (int s = 0; s < 4; s++) {
            unsigned af[2][4], bf[8][2];
#pragma unroll
            for (int mt = 0; mt < 2; mt++) {
                int r = wm * 32 + mt * 16 + lr;
                af[mt][0] = sA[adru(r, s * 8 + lq)];
                af[mt][1] = sA[adru(r + 8, s * 8 + lq)];
                af[mt][2] = sA[adru(r, s * 8 + 4 + lq)];
                af[mt][3] = sA[adru(r + 8, s * 8 + 4 + lq)];
            }
#pragma unroll
            for (int nt = 0; nt < 8; nt++) {
                int nn = wn * 64 + nt * 8 + lr;
                bf[nt][0] = sB[adru(nn, s * 8 + lq)];
                bf[nt][1] = sB[adru(nn, s * 8 + 4 + lq)];
            }
#pragma unroll
            for (int mt = 0; mt < 2; mt++)
#pragma unroll
                for (int nt = 0; nt < 8; nt++) MMA_BF16(acc[mt][nt], af[mt], bf[nt]);
        }
        __syncthreads();
    }

#pragma unroll
    for (int mt = 0; mt < 2; mt++)
#pragma unroll
        for (int nt = 0; nt < 8; nt++) {
            int r0 = row0 + wm * 32 + mt * 16 + lr;
            int cb = col0 + wn * 64 + nt * 8 + 2 * lq;
#pragma unroll
            for (int pe = 0; pe < 2; pe++) {
                int rr = r0 + pe * 8;
                float v0 = acc[mt][nt][pe * 2], v1 = acc[mt][nt][pe * 2 + 1];
                if (qkv) {
                    int i = rr >> 1, bb = rr & 1;
                    int sec = cb >> 10, c1 = cb & 1023, n = c1 >> 6, d = c1 & 63;
                    int z = bb * 16 + n;
                    if (sec == 0) {
                        long long idx = ((long long)z << 15) + (i << 5) + (d >> 1);
                        u1[idx] = packbf(v0 + bias1[c1], v1 + bias1[c1 + 1]);
                        u2[idx] = packbf(v0 + bias2[c1], v1 + bias2[c1 + 1]);
                    } else if (sec == 1) {
                        u3[((long long)z << 15) + (i << 5) + (d >> 1)] = packbf(v0, v1);
                    } else {
                        long long idx = ((long long)z << 16) + (i << 6) + d;
                        f4[idx] = v0; f4[idx + 1] = v1;
                    }
                } else {
                    if (bw) {
                        if (rr == 1023) continue;  // fw owns rk row 1023
                        rkb[(long long)rr * (-512) + (cb >> 1)] = packbf(v0, v1);
                    } else {
                        rkf[(long long)rr * 512 + (cb >> 1)] = packbf(v0, v1);
                    }
                }
            }
        }
}

// ---------------- merged V-transpose + BD band GEMM (mask folded into BD) ----------------
__global__ __launch_bounds__(256, 2) void vtbd_k(
    const unsigned* __restrict__ q2, const unsigned* __restrict__ rk,
    unsigned* __restrict__ bdu,
    const float* __restrict__ vv, unsigned* __restrict__ vvt,
    const unsigned char* __restrict__ msk) {
    extern __shared__ unsigned dsm[];
    int t = threadIdx.x, bid = blockIdx.x;
    if (bid < 2304) {
        unsigned* sA = dsm;
        unsigned* sB = dsm + 4096;
        int lane = t & 31, lq = lane & 3, lr = lane >> 2;
        int z = bid / 72, rem = bid % 72, b = z >> 4;
        int row0 = (rem / 9) * 128;
        int col0 = 896 - row0 + (rem % 9) * 128;
        const unsigned* Az = q2 + ((long long)z << 15);
        const unsigned* Bz = rk + (long long)(z & 15) * 32;
        unsigned* Cz = bdu + ((long long)z << 20);
        int warp = t >> 5, wm = warp >> 1, wn = warp & 1;

#pragma unroll
        for (int e = 0; e < 4; e++) {
            int c = e * 256 + t, r = c >> 3, c4 = c & 7;
            cp16(sA + r * 32 + ((c4 ^ (r & 7)) << 2), Az + (long long)(row0 + r) * 32 + c4 * 4);
            cp16(sB + r * 32 + ((c4 ^ (r & 7)) << 2), Bz + (long long)(col0 + r) * 512 + c4 * 4);
        }
        asm volatile("cp.async.commit_group;\ncp.async.wait_group 0;\n");
        __syncthreads();

        float acc[2][8][4] = {};
#pragma unroll
        for (int s = 0; s < 4; s++) {
            unsigned af[2][4], bf[8][2];
#pragma unroll
            for (int mt = 0; mt < 2; mt++) {
                int r = wm * 32 + mt * 16 + lr;
                af[mt][0] = sA[adru(r, s * 8 + lq)];
                af[mt][1] = sA[adru(r + 8, s * 8 + lq)];
                af[mt][2] = sA[adru(r, s * 8 + 4 + lq)];
                af[mt][3] = sA[adru(r + 8, s * 8 + 4 + lq)];
            }
#pragma unroll
            for (int nt = 0; nt < 8; nt++) {
                int nn = wn * 64 + nt * 8 + lr;
                bf[nt][0] = sB[adru(nn, s * 8 + lq)];
                bf[nt][1] = sB[adru(nn, s * 8 + 4 + lq)];
            }
#pragma unroll
            for (int mt = 0; mt < 2; mt++)
#pragma unroll
                for (int nt = 0; nt < 8; nt++) MMA_BF16(acc[mt][nt], af[mt], bf[nt]);
        }

#pragma unroll
        for (int mt = 0; mt < 2; mt++)
#pragma unroll
            for (int nt = 0; nt < 8; nt++) {
                int r0 = row0 + wm * 32 + mt * 16 + lr;
                int cb = col0 + wn * 64 + nt * 8 + 2 * lq;
#pragma unroll
                for (int pe = 0; pe < 2; pe++) {
                    int rr = r0 + pe * 8;
                    float v0 = acc[mt][nt][pe * 2], v1 = acc[mt][nt][pe * 2 + 1];
                    // fold mask: band col cb at row rr corresponds to key j = rr+cb-1023
                    int j = rr + cb - 1023;
                    if ((unsigned)j < 1024u && msk[j * 2 + b]) v0 = -1e38f;
                    if ((unsigned)(j + 1) < 1024u && msk[(j + 1) * 2 + b]) v1 = -1e38f;
                    Cz[((rr << 11) + cb) >> 1] = packbf(v0, v1);
                }
            }
    } else {
        float (*ts)[65] = (float(*)[65])dsm;
        int idx = bid - 2304;
        int z = idx >> 3, j0 = (idx & 7) * 128;
        const float* Vz = vv + ((long long)z << 16);
#pragma unroll
        for (int e = 0; e < 8; e++) {
            int c = e * 256 + t, r = c >> 4, c4 = c & 15;
            float4 v = *(const float4*)(Vz + (long long)(j0 + r) * 64 + c4 * 4);
            ts[r][c4 * 4] = v.x; ts[r][c4 * 4 + 1] = v.y;
            ts[r][c4 * 4 + 2] = v.z; ts[r][c4 * 4 + 3] = v.w;
        }
        __syncthreads();
#pragma unroll
        for (int e = 0; e < 16; e++) {
            int c = e * 256 + t, d = c >> 6, jp = c & 63;
            vvt[((long long)z << 15) + (d << 9) + (j0 >> 1) + jp] =
                packbf(ts[jp * 2][d], ts[jp * 2 + 1][d]);
        }
    }
}

// ---------------- bf16 GEMM 128x128 — Wo (fp32 store) ----------------
__global__ __launch_bounds__(256, 2) void wo_k(
    const unsigned* __restrict__ A, const unsigned* __restrict__ B,
    float* __restrict__ f4) {
    extern __shared__ unsigned su[];
    int t = threadIdx.x, lane = t & 31, lq = lane & 3, lr = lane >> 2;
    int row0 = blockIdx.y * 128, col0 = blockIdx.x * 128;
    int warp = t >> 5, wm = warp >> 1, wn = warp & 1;

    float acc[2][8][4] = {};

    auto load_tile = [&](int kt, int st) {
        unsigned* sA = su + st * 8192;
        unsigned* sB = sA + 4096;
        int k0 = kt * 32;
#pragma unroll
        for (int e = 0; e < 4; e++) {
            int c = e * 256 + t, r = c >> 3, c4 = c & 7;
            cp16(sA + r * 32 + ((c4 ^ (r & 7)) << 2),
                 A + (long long)(row0 + r) * 512 + k0 + c4 * 4);
            cp16(sB + r * 32 + ((c4 ^ (r & 7)) << 2),
                 B + (long long)(col0 + r) * 512 + k0 + c4 * 4);
        }
        asm volatile("cp.async.commit_group;\n");
    };

    load_tile(0, 0);
    for (int kt = 0; kt < 16; kt++) {
        int st = kt & 1;
        if (kt + 1 < 16) {
            load_tile(kt + 1, st ^ 1);
            asm volatile("cp.async.wait_group 1;\n");
        } else {
            asm volatile("cp.async.wait_group 0;\n");
        }
        __syncthreads();
        unsigned* sA = su + st * 8192;
        unsigned* sB = sA + 4096;
#pragma unroll
        for (int s = 0; s < 4; s++) {
            unsigned af[2][4], bf[8][2];
#pragma unroll
            for (int mt = 0; mt < 2; mt++) {
                int r = wm * 32 + mt * 16 + lr;
                af[mt][0] = sA[adru(r, s * 8 + lq)];
                af[mt][1] = sA[adru(r + 8, s * 8 + lq)];
                af[mt][2] = sA[adru(r, s * 8 + 4 + lq)];
                af[mt][3] = sA[adru(r + 8, s * 8 + 4 + lq)];
            }
#pragma unroll
            for (int nt = 0; nt < 8; nt++) {
                int nn = wn * 64 + nt * 8 + lr;
                bf[nt][0] = sB[adru(nn, s * 8 + lq)];
                bf[nt][1] = sB[adru(nn, s * 8 + 4 + lq)];
            }
#pragma unroll
            for (int mt = 0; mt < 2; mt++)
#pragma unroll
                for (int nt = 0; nt < 8; nt++) MMA_BF16(acc[mt][nt], af[mt], bf[nt]);
        }
        __syncthreads();
    }

#pragma unroll
    for (int mt = 0; mt < 2; mt++)
#pragma unroll
        for (int nt = 0; nt < 8; nt++) {
            int r0 = row0 + wm * 32 + mt * 16 + lr;
            int cb = col0 + wn * 64 + nt * 8 + 2 * lq;
#pragma unroll
            for (int pe = 0; pe < 2; pe++) {
                int rr = r0 + pe * 8;
                f4[(long long)rr * 1024 + cb] = acc[mt][nt][pe * 2];
                f4[(long long)rr * 1024 + cb + 1] = acc[mt][nt][pe * 2 + 1];
            }
        }
}

// ---------------- flash (bf16): S = Q1·K^T + BD_band(masked), softmax, P·V ----------------
// P stays in registers (C-frag of S == A-frag for PV). No sP, no sMask.
__global__ __launch_bounds__(256, 2) void flash_k(
    const unsigned* __restrict__ q1, const unsigned* __restrict__ kk,
    const unsigned* __restrict__ vvt, const __nv_bfloat16* __restrict__ bdh,
    unsigned* __restrict__ vecu) {
    extern __shared__ unsigned fsu[];
    unsigned* sQ = fsu;                // 128 x 32 u32
    unsigned* sK = sQ + 4096;          // 3 x 64 x 32 u32
    unsigned* sVt = sK + 3 * 2048;     // 3 x 64 x 32 u32 (rows = d)

    int t = threadIdx.x, lane = t & 31, warp = t >> 5;
    int lq = lane & 3, lr = lane >> 2;
    int i0 = blockIdx.x * 128, z = blockIdx.y, b = z >> 4, nh = z & 15;
    const unsigned* Qz = q1 + ((long long)z << 15);
    const unsigned* Kz = kk + ((long long)z << 15);
    const unsigned* Vtz = vvt + ((long long)z << 15);
    const __nv_bfloat16* bdz = bdh + ((long long)z << 21);

#pragma unroll
    for (int e = 0; e < 4; e++) {
        int c = e * 256 + t, r = c >> 3, c4 = c & 7;
        cp16(sQ + r * 32 + ((c4 ^ (r & 7)) << 2), Qz + (long long)(i0 + r) * 32 + c4 * 4);
    }
    auto loadKV = [&](int jt, int bufi) {
        unsigned* dK = sK + bufi * 2048;
        unsigned* dV = sVt + bufi * 2048;
        int j0 = jt * 64;
#pragma unroll
        for (int e = 0; e < 2; e++) {
            int c = e * 256 + t, r = c >> 3, c4 = c & 7;
            cp16(dK + r * 32 + ((c4 ^ (r & 7)) << 2), Kz + (long long)(j0 + r) * 32 + c4 * 4);
            cp16(dV + r * 32 + ((c4 ^ (r & 7)) << 2),
                 Vtz + ((long long)r << 9) + (j0 >> 1) + c4 * 4);
        }
        asm volatile("cp.async.commit_group;\n");
    };
    loadKV(0, 0);
    loadKV(1, 1);

    float mA = -3.4e38f, mB = -3.4e38f, lA = 0.f, lB = 0.f;
    float O[8][4] = {};
    int rb = warp * 16 + lr;
    int rowA = i0 + rb;
    const unsigned short* bd0 = (const unsigned short*)(bdz + (long long)rowA * 2048 + (1023 - rowA));
    const unsigned short* bd1 = (const unsigned short*)(bdz + (long long)(rowA + 8) * 2048 + (1015 - rowA));

    unsigned pbv[16];
    auto prefetchBD = [&](int jt) {
#pragma unroll
        for (int nt = 0; nt < 8; nt++) {
            int jc = jt * 64 + nt * 8 + 2 * lq;
            unsigned short l0 = __ldg(bd0 + jc), h0 = __ldg(bd0 + jc + 1);
            unsigned short l1 = __ldg(bd1 + jc), h1 = __ldg(bd1 + jc + 1);
            pbv[2 * nt] = (unsigned)l0 | ((unsigned)h0 << 16);
            pbv[2 * nt + 1] = (unsigned)l1 | ((unsigned)h1 << 16);
        }
    };
    prefetchBD(0);

    for (int jt = 0; jt < 16; jt++) {
        int buf = jt % 3;
        if (jt == 15) asm volatile("cp.async.wait_group 0;\n");
        else          asm volatile("cp.async.wait_group 1;\n");
        __syncthreads();

        // ---- S = Q1 @ K^T ----
        unsigned* cK = sK + buf * 2048;
        float S[8][4] = {};
#pragma unroll
        for (int s = 0; s < 4; s++) {
            unsigned a[4];
            a[0] = sQ[adru(rb, s * 8 + lq)];
            a[1] = sQ[adru(rb + 8, s * 8 + lq)];
            a[2] = sQ[adru(rb, s * 8 + 4 + lq)];
            a[3] = sQ[adru(rb + 8, s * 8 + 4 + lq)];
#pragma unroll
            for (int nt = 0; nt < 8; nt++) {
                int nn = nt * 8 + lr;
                unsigned bfx[2];
                bfx[0] = cK[adru(nn, s * 8 + lq)];
                bfx[1] = cK[adru(nn, s * 8 + 4 + lq)];
                MMA_BF16(S[nt], a, bfx);
            }
        }

        // ---- combine prefetched BD (mask pre-folded), scale ----
#pragma unroll
        for (int nt = 0; nt < 8; nt++) {
            float2 f0 = __bfloat1622float2(*reinterpret_cast<__nv_bfloat162*>(&pbv[2 * nt]));
            float2 f1 = __bfloat1622float2(*reinterpret_cast<__nv_bfloat162*>(&pbv[2 * nt + 1]));
            S[nt][0] = (S[nt][0] + f0.x) * SCALE_F;
            S[nt][1] = (S[nt][1] + f0.y) * SCALE_F;
            S[nt][2] = (S[nt][2] + f1.x) * SCALE_F;
            S[nt][3] = (S[nt][3] + f1.y) * SCALE_F;
        }

        // ---- online softmax (p kept in S registers) ----
        float mxA = -3.4e38f, mxB = -3.4e38f;
#pragma unroll
        for (int nt = 0; nt < 8; nt++) {
            mxA = fmaxf(mxA, fmaxf(S[nt][0], S[nt][1]));
            mxB = fmaxf(mxB, fmaxf(S[nt][2], S[nt][3]));
        }
        mxA = fmaxf(mxA, __shfl_xor_sync(0xffffffffu, mxA, 1));
        mxA = fmaxf(mxA, __shfl_xor_sync(0xffffffffu, mxA, 2));
        mxB = fmaxf(mxB, __shfl_xor_sync(0xffffffffu, mxB, 1));
        mxB = fmaxf(mxB, __shfl_xor_sync(0xffffffffu, mxB, 2));
        float nmA = fmaxf(mA, mxA), nmB = fmaxf(mB, mxB);
        float scA = __expf(mA - nmA), scB = __expf(mB - nmB);
        mA = nmA; mB = nmB;
        float smA = 0.f, smB = 0.f;
#pragma unroll
        for (int nt = 0; nt < 8; nt++) {
            S[nt][0] = __expf(S[nt][0] - nmA);
            S[nt][1] = __expf(S[nt][1] - nmA);
            S[nt][2] = __expf(S[nt][2] - nmB);
            S[nt][3] = __expf(S[nt][3] - nmB);
            smA += S[nt][0] + S[nt][1];
            smB += S[nt][2] + S[nt][3];
        }
        smA += __shfl_xor_sync(0xffffffffu, smA, 1);
        smA += __shfl_xor_sync(0xffffffffu, smA, 2);
        smB += __shfl_xor_sync(0xffffffffu, smB, 1);
        smB += __shfl_xor_sync(0xffffffffu, smB, 2);
        lA = lA * scA + smA;
        lB = lB * scB + smB;
#pragma unroll
        for (int nt = 0; nt < 8; nt++) {
            O[nt][0] *= scA; O[nt][1] *= scA;
            O[nt][2] *= scB; O[nt][3] *= scB;
        }

        // ---- O += P @ V with P formed in registers (C-frag == A-frag layout) ----
        unsigned* cV = sVt + buf * 2048;
#pragma unroll
        for (int s = 0; s < 4; s++) {
            unsigned a[4];
            a[0] = packbf(S[2 * s][0], S[2 * s][1]);
            a[1] = packbf(S[2 * s][2], S[2 * s][3]);
            a[2] = packbf(S[2 * s + 1][0], S[2 * s + 1][1]);
            a[3] = packbf(S[2 * s + 1][2], S[2 * s + 1][3]);
#pragma unroll
            for (int nt = 0; nt < 8; nt++) {
                int nn = nt * 8 + lr;
                unsigned bfx[2];
                bfx[0] = cV[adru(nn, s * 8 + lq)];
                bfx[1] = cV[adru(nn, s * 8 + 4 + lq)];
                MMA_BF16(O[nt], a, bfx);
            }
        }

        if (jt + 2 < 16) loadKV(jt + 2, (jt + 2) % 3);
        if (jt + 1 < 16) prefetchBD(jt + 1);
    }

    float iA = 1.0f / lA, iB = 1.0f / lB;
#pragma unroll
    for (int nt = 0; nt < 8; nt++) {
        int cp = (nh << 5) + nt * 4 + lq;
        vecu[(((long long)(rowA * 2 + b)) << 9) + cp] = packbf(O[nt][0] * iA, O[nt][1] * iA);
        vecu[(((long long)((rowA + 8) * 2 + b)) << 9) + cp] = packbf(O[nt][2] * iB, O[nt][3] * iB);
    }
}

// ---------------- residual + LayerNorm (float4) ----------------
__global__ void ln_k(const float* __restrict__ w, const float* __restrict__ xb,
                     const float* __restrict__ g, const float* __restrict__ bb,
                     float* __restrict__ out) {
    __shared__ float smr[16];
    int row = blockIdx.x, t = threadIdx.x;
    const float4* wr = (const float4*)(w + (long long)row * 1024);
    const float4* xr = (const float4*)(xb + (long long)row * 1024);
    float4 wv = wr[t], xv = xr[t];
    float l0 = wv.x + xv.x, l1 = wv.y + xv.y, l2 = wv.z + xv.z, l3 = wv.w + xv.w;
    float s = l0 + l1 + l2 + l3;
    float sq = l0 * l0 + l1 * l1 + l2 * l2 + l3 * l3;
#pragma unroll
    for (int o = 16; o; o >>= 1) {
        s += __shfl_xor_sync(0xffffffffu, s, o);
        sq += __shfl_xor_sync(0xffffffffu, sq, o);
    }
    if ((t & 31) == 0) { smr[t >> 5] = s; smr[8 + (t >> 5)] = sq; }
    __syncthreads();
    s = smr[t & 7]; sq = smr[8 + (t & 7)];
#pragma unroll
    for (int o = 4; o; o >>= 1) {
        s += __shfl_xor_sync(0xffffffffu, s, o);
        sq += __shfl_xor_sync(0xffffffffu, sq, o);
    }
    float mu = s * (1.0f / 1024.0f);
    float var = sq * (1.0f / 1024.0f) - mu * mu;
    float rstd = rsqrtf(var + EPS_F);
    float4 gv = ((const float4*)g)[t];
    float4 bv = ((const float4*)bb)[t];
    float4 ov;
    ov.x = (l0 - mu) * rstd * gv.x + bv.x;
    ov.y = (l1 - mu) * rstd * gv.y + bv.y;
    ov.z = (l2 - mu) * rstd * gv.z + bv.z;
    ov.w = (l3 - mu) * rstd * gv.w + bv.w;
    ((float4*)(out + (long long)row * 1024))[t] = ov;
}

// ---------------- launch ----------------
extern "C" void kernel_launch(void* const* d_in, const int* in_sizes, int n_in,
                              void* d_out, int out_size) {
    const float* w    = (const float*)d_in[0];
    const float* r    = (const float*)d_in[1];
    const float* rwb  = (const float*)d_in[2];
    const float* rrb  = (const float*)d_in[3];
    const unsigned char* mask = (const unsigned char*)d_in[4];
    const float* Wqkv = (const float*)d_in[5];
    const float* Wrfw = (const float*)d_in[6];
    const float* Wrbw = (const float*)d_in[7];
    const float* Wo   = (const float*)d_in[8];
    const float* lng  = (const float*)d_in[9];
    const float* lnb  = (const float*)d_in[10];
    float* out = (float*)d_out;

    unsigned *wu, *ru, *WqkvT, *WrfwT, *WrbwT, *WoT;
    unsigned *q1u, *q2u, *kku, *rku, *vvt, *vecu;
    __nv_bfloat16* bdh;
    float *vv, *xb;
    cudaGetSymbolAddress((void**)&wu, g_wu);
    cudaGetSymbolAddress((void**)&ru, g_ru);
    cudaGetSymbolAddress((void**)&WqkvT, g_WqkvT);
    cudaGetSymbolAddress((void**)&WrfwT, g_WrfwT);
    cudaGetSymbolAddress((void**)&WrbwT, g_WrbwT);
    cudaGetSymbolAddress((void**)&WoT, g_WoT);
    cudaGetSymbolAddress((void**)&q1u, g_q1u);
    cudaGetSymbolAddress((void**)&q2u, g_q2u);
    cudaGetSymbolAddress((void**)&kku, g_kku);
    cudaGetSymbolAddress((void**)&vv, g_vv);
    cudaGetSymbolAddress((void**)&vvt, g_vvt);
    cudaGetSymbolAddress((void**)&rku, g_rku);
    cudaGetSymbolAddress((void**)&bdh, g_bdh);
    cudaGetSymbolAddress((void**)&vecu, g_vecu);
    cudaGetSymbolAddress((void**)&xb, g_x);

    prep_k<<<7682, 256>>>(w, wu, r, ru, Wqkv, WqkvT, Wrfw, WrfwT,
                          Wrbw, WrbwT, Wo, WoT, rku + 2047 * 512);

    int bg_smem = 2 * 8192 * 4;  // 64 KB
    cudaFuncSetAttribute(gemms_k, cudaFuncAttributeMaxDynamicSharedMemorySize, bg_smem);
    cudaFuncSetAttribute(wo_k, cudaFuncAttributeMaxDynamicSharedMemorySize, bg_smem);

    gemms_k<<<512, 256, bg_smem>>>(wu, WqkvT, rwb, rrb, q1u, q2u, kku, vv,
                                   ru, WrfwT, WrbwT, rku, rku + 2046 * 512);

    int vb_smem = 130 * 256 + 1024;
    cudaFuncSetAttribute(vtbd_k, cudaFuncAttributeMaxDynamicSharedMemorySize, vb_smem);
    vtbd_k<<<2560, 256, vb_smem>>>(q2u, rku, (unsigned*)bdh, vv, vvt, mask);

    int fl_smem = (4096 + 3 * 2048 + 3 * 2048) * 4;  // 64 KB (no sP/sMask)
    cudaFuncSetAttribute(flash_k, cudaFuncAttributeMaxDynamicSharedMemorySize, fl_smem);
    flash_k<<<dim3(8, 32), 256, fl_smem>>>(q1u, kku, vvt, bdh, vecu);

    wo_k<<<dim3(8, 16), 256, bg_smem>>>(vecu, WoT, xb);

    ln_k<<<2048, 256>>>(w, xb, lng, lnb, out);
}

// round 17
// speedup vs baseline: 1.2919x; 1.1879x over previous
#include <cuda_runtime.h>
#include <cuda_bf16.h>
#include <math.h>

#define SCALE_F 0.125f
#define EPS_F 1e-5f

// ---------------- scratch (device globals) ----------------
__device__ unsigned g_wu[2048 * 512];
__device__ unsigned g_ru[1024 * 512];
__device__ unsigned g_WqkvT[3072 * 512];
__device__ unsigned g_WrfwT[1024 * 512];
__device__ unsigned g_WrbwT[1024 * 512];
__device__ unsigned g_WoT[1024 * 512];
__device__ unsigned g_q1u[32 * 1024 * 32];
__device__ unsigned g_q2u[32 * 1024 * 32];
__device__ unsigned g_kku[32 * 1024 * 32];
__device__ float    g_vv[32 * 1024 * 64];
__device__ unsigned g_vvt[32 * 64 * 512];
__device__ unsigned g_rku[2048 * 512];
__device__ __nv_bfloat16 g_bdh[67108864];   // BD band; masked cells = -1e38
__device__ unsigned g_vecu[2048 * 512];
__device__ float    g_x[2048 * 1024];

// ---------------- helpers ----------------
__device__ __forceinline__ void cp16(void* s, const void* g) {
    unsigned a = (unsigned)__cvta_generic_to_shared(s);
    asm volatile("cp.async.cg.shared.global [%0], [%1], 16;\n" ::"r"(a), "l"(g));
}
__device__ __forceinline__ unsigned packbf(float lo, float hi) {
    unsigned u;
    asm("cvt.rn.bf16x2.f32 %0, %1, %2;" : "=r"(u) : "f"(hi), "f"(lo));
    return u;
}
__device__ __forceinline__ int adru(int r, int c) {  // bf16x2 rows of 32 u32, XOR swizzle
    return r * 32 + (((c >> 2) ^ (r & 7)) << 2) + (c & 3);
}
// byte smem address of the 16B row-segment (row r, u32-group g) in adru layout
__device__ __forceinline__ unsigned seg_addr(unsigned base, int r, int g) {
    return base + (unsigned)(((r << 5) + ((g ^ (r & 7)) << 2)) << 2);
}
__device__ __forceinline__ void ldm4(unsigned d[4], unsigned sa) {
    asm volatile("ldmatrix.sync.aligned.m8n8.x4.shared.b16 {%0,%1,%2,%3}, [%4];"
                 : "=r"(d[0]), "=r"(d[1]), "=r"(d[2]), "=r"(d[3]) : "r"(sa));
}
#define MMA_BF16(c, a0, a1, a2, a3, b0, b1)                                        \
    asm volatile(                                                                  \
        "mma.sync.aligned.m16n8k16.row.col.f32.bf16.bf16.f32 "                     \
        "{%0,%1,%2,%3},{%4,%5,%6,%7},{%8,%9},{%0,%1,%2,%3};"                       \
        : "+f"(c[0]), "+f"(c[1]), "+f"(c[2]), "+f"(c[3])                           \
        : "r"(a0), "r"(a1), "r"(a2), "r"(a3), "r"(b0), "r"(b1))

// ---------------- merged prep ----------------
__device__ __forceinline__ void packT_body2(const float* in, unsigned* out, int N,
                                            int n0, int k0, float (*ts)[65]) {
    int t = threadIdx.x;
#pragma unroll
    for (int e = 0; e < 16; e++) {
        int idx = e * 256 + t, kk = idx >> 6, nn = idx & 63;
        ts[kk][nn] = in[(long long)(k0 + kk) * N + n0 + nn];
    }
    __syncthreads();
#pragma unroll
    for (int e = 0; e < 8; e++) {
        int idx = e * 256 + t, nn = idx >> 5, kp = idx & 31;
        out[(long long)(n0 + nn) * 512 + (k0 >> 1) + kp] =
            packbf(ts[2 * kp][nn], ts[2 * kp + 1][nn]);
    }
}
__global__ __launch_bounds__(256) void prep_k(
    const float* __restrict__ w, unsigned* __restrict__ wu,
    const float* __restrict__ r, unsigned* __restrict__ ru,
    const float* __restrict__ Wqkv, unsigned* __restrict__ WqkvT,
    const float* __restrict__ Wrfw, unsigned* __restrict__ WrfwT,
    const float* __restrict__ Wrbw, unsigned* __restrict__ WrbwT,
    const float* __restrict__ Wo, unsigned* __restrict__ WoT,
    unsigned* __restrict__ rkpad) {
    __shared__ float ts[64][65];
    int b = blockIdx.x;
    if (b < 4096) {
        int i = b * 256 + threadIdx.x;
        float2 v = ((const float2*)w)[i];
        wu[i] = packbf(v.x, v.y);
    } else if (b < 6144) {
        int i = (b - 4096) * 256 + threadIdx.x;
        float2 v = ((const float2*)r)[i];
        ru[i] = packbf(v.x, v.y);
    } else if (b < 6912) {
        int idx = b - 6144;
        packT_body2(Wqkv, WqkvT, 3072, (idx % 48) * 64, (idx / 48) * 64, ts);
    } else if (b < 7680) {
        int idx = b - 6912;
        int zsel = idx >> 8; idx &= 255;
        const float* in = (zsel == 0) ? Wrfw : (zsel == 1) ? Wrbw : Wo;
        unsigned* outp = (zsel == 0) ? WrfwT : (zsel == 1) ? WrbwT : WoT;
        packT_body2(in, outp, 1024, (idx & 15) * 64, (idx >> 4) * 64, ts);
    } else {
        rkpad[(b - 7680) * 256 + threadIdx.x] = 0u;
    }
}

// ---------------- shared GEMM mainloop body (ldmatrix frags) ----------------
// computes 128x128 with A rows [row0..], B rows [col0..], K=1024 (16 chunks of 32 u32)
#define GEMM_MAIN(Aptr, Bptr, suPtr)                                               \
    auto load_tile = [&](int kt, int st) {                                         \
        unsigned* sA = suPtr + st * 8192;                                          \
        unsigned* sB = sA + 4096;                                                  \
        int k0 = kt * 32;                                                          \
        _Pragma("unroll")                                                          \
        for (int e = 0; e < 4; e++) {                                              \
            int c = e * 256 + t, r = c >> 3, c4 = c & 7;                           \
            cp16(sA + r * 32 + ((c4 ^ (r & 7)) << 2),                              \
                 Aptr + (long long)(row0 + r) * 512 + k0 + c4 * 4);                \
            cp16(sB + r * 32 + ((c4 ^ (r & 7)) << 2),                              \
                 Bptr + (long long)(col0 + r) * 512 + k0 + c4 * 4);                \
        }                                                                          \
        asm volatile("cp.async.commit_group;\n");                                  \
    };                                                                             \
    load_tile(0, 0);                                                               \
    for (int kt = 0; kt < 16; kt++) {                                              \
        int st = kt & 1;                                                           \
        if (kt + 1 < 16) {                                                         \
            load_tile(kt + 1, st ^ 1);                                             \
            asm volatile("cp.async.wait_group 1;\n");                              \
        } else {                                                                   \
            asm volatile("cp.async.wait_group 0;\n");                              \
        }                                                                          \
        __syncthreads();                                                           \
        unsigned sAb = subase + (unsigned)(st * 8192 * 4);                         \
        unsigned sBb = sAb + 4096 * 4;                                             \
        _Pragma("unroll")                                                          \
        for (int s = 0; s < 4; s++) {                                              \
            unsigned af[2][4], bf[8][2];                                           \
            _Pragma("unroll")                                                      \
            for (int mt = 0; mt < 2; mt++)                                         \
                ldm4(af[mt], seg_addr(sAb, wm * 32 + mt * 16 + rOffA, 2 * s + gOffA)); \
            _Pragma("unroll")                                                      \
            for (int p = 0; p < 4; p++) {                                          \
                unsigned d[4];                                                     \
                ldm4(d, seg_addr(sBb, wn * 64 + 16 * p + rOffB, 2 * s + gOffB));   \
                bf[2 * p][0] = d[0]; bf[2 * p][1] = d[1];                          \
                bf[2 * p + 1][0] = d[2]; bf[2 * p + 1][1] = d[3];                  \
            }                                                                      \
            _Pragma("unroll")                                                      \
            for (int mt = 0; mt < 2; mt++)                                         \
                _Pragma("unroll")                                                  \
                for (int nt = 0; nt < 8; nt++)                                     \
                    MMA_BF16(acc[mt][nt], af[mt][0], af[mt][1], af[mt][2], af[mt][3], \
                             bf[nt][0], bf[nt][1]);                                \
        }                                                                          \
        __syncthreads();                                                           \
    }

// ---------------- merged QKV + rk GEMM ----------------
__global__ __launch_bounds__(256, 2) void gemms_k(
    const unsigned* __restrict__ Aq, const unsigned* __restrict__ Bq,
    const float* __restrict__ bias1, const float* __restrict__ bias2,
    unsigned* __restrict__ u1, unsigned* __restrict__ u2, unsigned* __restrict__ u3,
    float* __restrict__ f4,
    const unsigned* __restrict__ Ar, const unsigned* __restrict__ Bfw,
    const unsigned* __restrict__ Bbw,
    unsigned* __restrict__ rkf, unsigned* __restrict__ rkb) {
    extern __shared__ unsigned su[];
    unsigned subase = (unsigned)__cvta_generic_to_shared(su);
    int t = threadIdx.x, lane = t & 31, lq = lane & 3, lr = lane >> 2;
    int rOffA = ((lane >> 3) & 1) * 8 + (lane & 7), gOffA = lane >> 4;
    int rOffB = (lane >> 4) * 8 + (lane & 7), gOffB = (lane >> 3) & 1;
    int bid = blockIdx.x;
    bool qkv = bid < 384;
    const unsigned* A;
    const unsigned* B;
    int row0, col0;
    bool bw = false;
    if (qkv) {
        A = Aq; B = Bq;
        col0 = (bid % 24) * 128;
        row0 = (bid / 24) * 128;
    } else {
        int idx = bid - 384;
        int bx = idx & 15;
        row0 = (idx >> 4) * 128;
        col0 = (bx & 7) * 128;
        bw = bx >= 8;
        A = Ar; B = bw ? Bbw : Bfw;
    }
    int warp = t >> 5, wm = warp >> 1, wn = warp & 1;

    float acc[2][8][4] = {};
    GEMM_MAIN(A, B, su)

#pragma unroll
    for (int mt = 0; mt < 2; mt++)
#pragma unroll
        for (int nt = 0; nt < 8; nt++) {
            int r0 = row0 + wm * 32 + mt * 16 + lr;
            int cb = col0 + wn * 64 + nt * 8 + 2 * lq;
#pragma unroll
            for (int pe = 0; pe < 2; pe++) {
                int rr = r0 + pe * 8;
                float v0 = acc[mt][nt][pe * 2], v1 = acc[mt][nt][pe * 2 + 1];
                if (qkv) {
                    int i = rr >> 1, bb = rr & 1;
                    int sec = cb >> 10, c1 = cb & 1023, n = c1 >> 6, d = c1 & 63;
                    int z = bb * 16 + n;
                    if (sec == 0) {
                        long long idx = ((long long)z << 15) + (i << 5) + (d >> 1);
                        u1[idx] = packbf(v0 + bias1[c1], v1 + bias1[c1 + 1]);
                        u2[idx] = packbf(v0 + bias2[c1], v1 + bias2[c1 + 1]);
                    } else if (sec == 1) {
                        u3[((long long)z << 15) + (i << 5) + (d >> 1)] = packbf(v0, v1);
                    } else {
                        long long idx = ((long long)z << 16) + (i << 6) + d;
                        f4[idx] = v0; f4[idx + 1] = v1;
                    }
                } else {
                    if (bw) {
                        if (rr == 1023) continue;
                        rkb[(long long)rr * (-512) + (cb >> 1)] = packbf(v0, v1);
                    } else {
                        rkf[(long long)rr * 512 + (cb >> 1)] = packbf(v0, v1);
                    }
                }
            }
        }
}

// ---------------- merged V-transpose + BD band GEMM (mask folded) ----------------
__global__ __launch_bounds__(256, 2) void vtbd_k(
    const unsigned* __restrict__ q2, const unsigned* __restrict__ rk,
    unsigned* __restrict__ bdu,
    const float* __restrict__ vv, unsigned* __restrict__ vvt,
    const unsigned char* __restrict__ msk) {
    extern __shared__ unsigned dsm[];
    int t = threadIdx.x, bid = blockIdx.x;
    if (bid < 2304) {
        unsigned* sA = dsm;
        unsigned* sB = dsm + 4096;
        unsigned sAb = (unsigned)__cvta_generic_to_shared(sA);
        unsigned sBb = (unsigned)__cvta_generic_to_shared(sB);
        int lane = t & 31, lq = lane & 3, lr = lane >> 2;
        int rOffA = ((lane >> 3) & 1) * 8 + (lane & 7), gOffA = lane >> 4;
        int rOffB = (lane >> 4) * 8 + (lane & 7), gOffB = (lane >> 3) & 1;
        int z = bid / 72, rem = bid % 72, b = z >> 4;
        int row0 = (rem / 9) * 128;
        int col0 = 896 - row0 + (rem % 9) * 128;
        const unsigned* Az = q2 + ((long long)z << 15);
        const unsigned* Bz = rk + (long long)(z & 15) * 32;
        unsigned* Cz = bdu + ((long long)z << 20);
        int warp = t >> 5, wm = warp >> 1, wn = warp & 1;

#pragma unroll
        for (int e = 0; e < 4; e++) {
            int c = e * 256 + t, r = c >> 3, c4 = c & 7;
            cp16(sA + r * 32 + ((c4 ^ (r & 7)) << 2), Az + (long long)(row0 + r) * 32 + c4 * 4);
            cp16(sB + r * 32 + ((c4 ^ (r & 7)) << 2), Bz + (long long)(col0 + r) * 512 + c4 * 4);
        }
        asm volatile("cp.async.commit_group;\ncp.async.wait_group 0;\n");
        __syncthreads();

        float acc[2][8][4] = {};
#pragma unroll
        for (int s = 0; s < 4; s++) {
            unsigned af[2][4], bf[8][2];
#pragma unroll
            for (int mt = 0; mt < 2; mt++)
                ldm4(af[mt], seg_addr(sAb, wm * 32 + mt * 16 + rOffA, 2 * s + gOffA));
#pragma unroll
            for (int p = 0; p < 4; p++) {
                unsigned d[4];
                ldm4(d, seg_addr(sBb, wn * 64 + 16 * p + rOffB, 2 * s + gOffB));
                bf[2 * p][0] = d[0]; bf[2 * p][1] = d[1];
                bf[2 * p + 1][0] = d[2]; bf[2 * p + 1][1] = d[3];
            }
#pragma unroll
            for (int mt = 0; mt < 2; mt++)
#pragma unroll
                for (int nt = 0; nt < 8; nt++)
                    MMA_BF16(acc[mt][nt], af[mt][0], af[mt][1], af[mt][2], af[mt][3],
                             bf[nt][0], bf[nt][1]);
        }

#pragma unroll
        for (int mt = 0; mt < 2; mt++)
#pragma unroll
            for (int nt = 0; nt < 8; nt++) {
                int r0 = row0 + wm * 32 + mt * 16 + lr;
                int cb = col0 + wn * 64 + nt * 8 + 2 * lq;
#pragma unroll
                for (int pe = 0; pe < 2; pe++) {
                    int rr = r0 + pe * 8;
                    float v0 = acc[mt][nt][pe * 2], v1 = acc[mt][nt][pe * 2 + 1];
                    int j = rr + cb - 1023;
                    if ((unsigned)j < 1024u && msk[j * 2 + b]) v0 = -1e38f;
                    if ((unsigned)(j + 1) < 1024u && msk[(j + 1) * 2 + b]) v1 = -1e38f;
                    Cz[((rr << 11) + cb) >> 1] = packbf(v0, v1);
                }
            }
    } else {
        float (*ts)[65] = (float(*)[65])dsm;
        int idx = bid - 2304;
        int z = idx >> 3, j0 = (idx & 7) * 128;
        const float* Vz = vv + ((long long)z << 16);
#pragma unroll
        for (int e = 0; e < 8; e++) {
            int c = e * 256 + t, r = c >> 4, c4 = c & 15;
            float4 v = *(const float4*)(Vz + (long long)(j0 + r) * 64 + c4 * 4);
            ts[r][c4 * 4] = v.x; ts[r][c4 * 4 + 1] = v.y;
            ts[r][c4 * 4 + 2] = v.z; ts[r][c4 * 4 + 3] = v.w;
        }
        __syncthreads();
#pragma unroll
        for (int e = 0; e < 16; e++) {
            int c = e * 256 + t, d = c >> 6, jp = c & 63;
            vvt[((long long)z << 15) + (d << 9) + (j0 >> 1) + jp] =
                packbf(ts[jp * 2][d], ts[jp * 2 + 1][d]);
        }
    }
}

// ---------------- Wo GEMM (fp32 store) ----------------
__global__ __launch_bounds__(256, 2) void wo_k(
    const unsigned* __restrict__ A, const unsigned* __restrict__ B,
    float* __restrict__ f4) {
    extern __shared__ unsigned su[];
    unsigned subase = (unsigned)__cvta_generic_to_shared(su);
    int t = threadIdx.x, lane = t & 31, lq = lane & 3, lr = lane >> 2;
    int rOffA = ((lane >> 3) & 1) * 8 + (lane & 7), gOffA = lane >> 4;
    int rOffB = (lane >> 4) * 8 + (lane & 7), gOffB = (lane >> 3) & 1;
    int row0 = blockIdx.y * 128, col0 = blockIdx.x * 128;
    int warp = t >> 5, wm = warp >> 1, wn = warp & 1;

    float acc[2][8][4] = {};
    GEMM_MAIN(A, B, su)

#pragma unroll
    for (int mt = 0; mt < 2; mt++)
#pragma unroll
        for (int nt = 0; nt < 8; nt++) {
            int r0 = row0 + wm * 32 + mt * 16 + lr;
            int cb = col0 + wn * 64 + nt * 8 + 2 * lq;
#pragma unroll
            for (int pe = 0; pe < 2; pe++) {
                int rr = r0 + pe * 8;
                f4[(long long)rr * 1024 + cb] = acc[mt][nt][pe * 2];
                f4[(long long)rr * 1024 + cb + 1] = acc[mt][nt][pe * 2 + 1];
            }
        }
}

// ---------------- flash (bf16, ldmatrix frags, P in registers) ----------------
__global__ __launch_bounds__(256, 2) void flash_k(
    const unsigned* __restrict__ q1, const unsigned* __restrict__ kk,
    const unsigned* __restrict__ vvt, const __nv_bfloat16* __restrict__ bdh,
    unsigned* __restrict__ vecu) {
    extern __shared__ unsigned fsu[];
    unsigned* sQ = fsu;                // 128 x 32 u32
    unsigned* sK = sQ + 4096;          // 3 x 64 x 32 u32
    unsigned* sVt = sK + 3 * 2048;     // 3 x 64 x 32 u32
    unsigned sQb = (unsigned)__cvta_generic_to_shared(sQ);
    unsigned sKb = (unsigned)__cvta_generic_to_shared(sK);
    unsigned sVb = (unsigned)__cvta_generic_to_shared(sVt);

    int t = threadIdx.x, lane = t & 31, warp = t >> 5;
    int lq = lane & 3, lr = lane >> 2;
    int rOffA = ((lane >> 3) & 1) * 8 + (lane & 7), gOffA = lane >> 4;
    int rOffB = (lane >> 4) * 8 + (lane & 7), gOffB = (lane >> 3) & 1;
    int i0 = blockIdx.x * 128, z = blockIdx.y, b = z >> 4, nh = z & 15;
    const unsigned* Qz = q1 + ((long long)z << 15);
    const unsigned* Kz = kk + ((long long)z << 15);
    const unsigned* Vtz = vvt + ((long long)z << 15);
    const __nv_bfloat16* bdz = bdh + ((long long)z << 21);

#pragma unroll
    for (int e = 0; e < 4; e++) {
        int c = e * 256 + t, r = c >> 3, c4 = c & 7;
        cp16(sQ + r * 32 + ((c4 ^ (r & 7)) << 2), Qz + (long long)(i0 + r) * 32 + c4 * 4);
    }
    auto loadKV = [&](int jt, int bufi) {
        unsigned* dK = sK + bufi * 2048;
        unsigned* dV = sVt + bufi * 2048;
        int j0 = jt * 64;
#pragma unroll
        for (int e = 0; e < 2; e++) {
            int c = e * 256 + t, r = c >> 3, c4 = c & 7;
            cp16(dK + r * 32 + ((c4 ^ (r & 7)) << 2), Kz + (long long)(j0 + r) * 32 + c4 * 4);
            cp16(dV + r * 32 + ((c4 ^ (r & 7)) << 2),
                 Vtz + ((long long)r << 9) + (j0 >> 1) + c4 * 4);
        }
        asm volatile("cp.async.commit_group;\n");
    };
    loadKV(0, 0);
    loadKV(1, 1);

    float mA = -3.4e38f, mB = -3.4e38f, lA = 0.f, lB = 0.f;
    float O[8][4] = {};
    int rb = warp * 16 + lr;
    int rowA = i0 + rb;
    const unsigned short* bd0 = (const unsigned short*)(bdz + (long long)rowA * 2048 + (1023 - rowA));
    const unsigned short* bd1 = (const unsigned short*)(bdz + (long long)(rowA + 8) * 2048 + (1015 - rowA));

    unsigned pbv[16];
    auto prefetchBD = [&](int jt) {
#pragma unroll
        for (int nt = 0; nt < 8; nt++) {
            int jc = jt * 64 + nt * 8 + 2 * lq;
            unsigned short l0 = __ldg(bd0 + jc), h0 = __ldg(bd0 + jc + 1);
            unsigned short l1 = __ldg(bd1 + jc), h1 = __ldg(bd1 + jc + 1);
            pbv[2 * nt] = (unsigned)l0 | ((unsigned)h0 << 16);
            pbv[2 * nt + 1] = (unsigned)l1 | ((unsigned)h1 << 16);
        }
    };
    prefetchBD(0);

    for (int jt = 0; jt < 16; jt++) {
        int buf = jt % 3;
        if (jt == 15) asm volatile("cp.async.wait_group 0;\n");
        else          asm volatile("cp.async.wait_group 1;\n");
        __syncthreads();

        // ---- S = Q1 @ K^T (ldmatrix frags) ----
        unsigned cKb = sKb + (unsigned)(buf * 2048 * 4);
        float S[8][4] = {};
#pragma unroll
        for (int s = 0; s < 4; s++) {
            unsigned a[4];
            ldm4(a, seg_addr(sQb, warp * 16 + rOffA, 2 * s + gOffA));
#pragma unroll
            for (int p = 0; p < 4; p++) {
                unsigned d[4];
                ldm4(d, seg_addr(cKb, 16 * p + rOffB, 2 * s + gOffB));
                MMA_BF16(S[2 * p], a[0], a[1], a[2], a[3], d[0], d[1]);
                MMA_BF16(S[2 * p + 1], a[0], a[1], a[2], a[3], d[2], d[3]);
            }
        }

        // ---- combine prefetched BD (mask pre-folded), scale ----
#pragma unroll
        for (int nt = 0; nt < 8; nt++) {
            float2 f0 = __bfloat1622float2(*reinterpret_cast<__nv_bfloat162*>(&pbv[2 * nt]));
            float2 f1 = __bfloat1622float2(*reinterpret_cast<__nv_bfloat162*>(&pbv[2 * nt + 1]));
            S[nt][0] = (S[nt][0] + f0.x) * SCALE_F;
            S[nt][1] = (S[nt][1] + f0.y) * SCALE_F;
            S[nt][2] = (S[nt][2] + f1.x) * SCALE_F;
            S[nt][3] = (S[nt][3] + f1.y) * SCALE_F;
        }

        // ---- online softmax (p in registers) ----
        float mxA = -3.4e38f, mxB = -3.4e38f;
#pragma unroll
        for (int nt = 0; nt < 8; nt++) {
            mxA = fmaxf(mxA, fmaxf(S[nt][0], S[nt][1]));
            mxB = fmaxf(mxB, fmaxf(S[nt][2], S[nt][3]));
        }
        mxA = fmaxf(mxA, __shfl_xor_sync(0xffffffffu, mxA, 1));
        mxA = fmaxf(mxA, __shfl_xor_sync(0xffffffffu, mxA, 2));
        mxB = fmaxf(mxB, __shfl_xor_sync(0xffffffffu, mxB, 1));
        mxB = fmaxf(mxB, __shfl_xor_sync(0xffffffffu, mxB, 2));
        float nmA = fmaxf(mA, mxA), nmB = fmaxf(mB, mxB);
        float scA = __expf(mA - nmA), scB = __expf(mB - nmB);
        mA = nmA; mB = nmB;
        float smA = 0.f, smB = 0.f;
#pragma unroll
        for (int nt = 0; nt < 8; nt++) {
            S[nt][0] = __expf(S[nt][0] - nmA);
            S[nt][1] = __expf(S[nt][1] - nmA);
            S[nt][2] = __expf(S[nt][2] - nmB);
            S[nt][3] = __expf(S[nt][3] - nmB);
            smA += S[nt][0] + S[nt][1];
            smB += S[nt][2] + S[nt][3];
        }
        smA += __shfl_xor_sync(0xffffffffu, smA, 1);
        smA += __shfl_xor_sync(0xffffffffu, smA, 2);
        smB += __shfl_xor_sync(0xffffffffu, smB, 1);
        smB += __shfl_xor_sync(0xffffffffu, smB, 2);
        lA = lA * scA + smA;
        lB = lB * scB + smB;
#pragma unroll
        for (int nt = 0; nt < 8; nt++) {
            O[nt][0] *= scA; O[nt][1] *= scA;
            O[nt][2] *= scB; O[nt][3] *= scB;
        }

        // ---- O += P @ V (P in registers; V frags via ldmatrix) ----
        unsigned cVb = sVb + (unsigned)(buf * 2048 * 4);
#pragma unroll
        for (int s = 0; s < 4; s++) {
            unsigned a0 = packbf(S[2 * s][0], S[2 * s][1]);
            unsigned a1 = packbf(S[2 * s][2], S[2 * s][3]);
            unsigned a2 = packbf(S[2 * s + 1][0], S[2 * s + 1][1]);
            unsigned a3 = packbf(S[2 * s + 1][2], S[2 * s + 1][3]);
#pragma unroll
            for (int p = 0; p < 4; p++) {
                unsigned d[4];
                ldm4(d, seg_addr(cVb, 16 * p + rOffB, 2 * s + gOffB));
                MMA_BF16(O[2 * p], a0, a1, a2, a3, d[0], d[1]);
                MMA_BF16(O[2 * p + 1], a0, a1, a2, a3, d[2], d[3]);
            }
        }

        if (jt + 2 < 16) loadKV(jt + 2, (jt + 2) % 3);
        if (jt + 1 < 16) prefetchBD(jt + 1);
    }

    float iA = 1.0f / lA, iB = 1.0f / lB;
#pragma unroll
    for (int nt = 0; nt < 8; nt++) {
        int cp = (nh << 5) + nt * 4 + lq;
        vecu[(((long long)(rowA * 2 + b)) << 9) + cp] = packbf(O[nt][0] * iA, O[nt][1] * iA);
        vecu[(((long long)((rowA + 8) * 2 + b)) << 9) + cp] = packbf(O[nt][2] * iB, O[nt][3] * iB);
    }
}

// ---------------- residual + LayerNorm (float4) ----------------
__global__ void ln_k(const float* __restrict__ w, const float* __restrict__ xb,
                     const float* __restrict__ g, const float* __restrict__ bb,
                     float* __restrict__ out) {
    __shared__ float smr[16];
    int row = blockIdx.x, t = threadIdx.x;
    const float4* wr = (const float4*)(w + (long long)row * 1024);
    const float4* xr = (const float4*)(xb + (long long)row * 1024);
    float4 wv = wr[t], xv = xr[t];
    float l0 = wv.x + xv.x, l1 = wv.y + xv.y, l2 = wv.z + xv.z, l3 = wv.w + xv.w;
    float s = l0 + l1 + l2 + l3;
    float sq = l0 * l0 + l1 * l1 + l2 * l2 + l3 * l3;
#pragma unroll
    for (int o = 16; o; o >>= 1) {
        s += __shfl_xor_sync(0xffffffffu, s, o);
        sq += __shfl_xor_sync(0xffffffffu, sq, o);
    }
    if ((t & 31) == 0) { smr[t >> 5] = s; smr[8 + (t >> 5)] = sq; }
    __syncthreads();
    s = smr[t & 7]; sq = smr[8 + (t & 7)];
#pragma unroll
    for (int o = 4; o; o >>= 1) {
        s += __shfl_xor_sync(0xffffffffu, s, o);
        sq += __shfl_xor_sync(0xffffffffu, sq, o);
    }
    float mu = s * (1.0f / 1024.0f);
    float var = sq * (1.0f / 1024.0f) - mu * mu;
    float rstd = rsqrtf(var + EPS_F);
    float4 gv = ((const float4*)g)[t];
    float4 bv = ((const float4*)bb)[t];
    float4 ov;
    ov.x = (l0 - mu) * rstd * gv.x + bv.x;
    ov.y = (l1 - mu) * rstd * gv.y + bv.y;
    ov.z = (l2 - mu) * rstd * gv.z + bv.z;
    ov.w = (l3 - mu) * rstd * gv.w + bv.w;
    ((float4*)(out + (long long)row * 1024))[t] = ov;
}

// ---------------- launch ----------------
extern "C" void kernel_launch(void* const* d_in, const int* in_sizes, int n_in,
                              void* d_out, int out_size) {
    const float* w    = (const float*)d_in[0];
    const float* r    = (const float*)d_in[1];
    const float* rwb  = (const float*)d_in[2];
    const float* rrb  = (const float*)d_in[3];
    const unsigned char* mask = (const unsigned char*)d_in[4];
    const float* Wqkv = (const float*)d_in[5];
    const float* Wrfw = (const float*)d_in[6];
    const float* Wrbw = (const float*)d_in[7];
    const float* Wo   = (const float*)d_in[8];
    const float* lng  = (const float*)d_in[9];
    const float* lnb  = (const float*)d_in[10];
    float* out = (float*)d_out;

    unsigned *wu, *ru, *WqkvT, *WrfwT, *WrbwT, *WoT;
    unsigned *q1u, *q2u, *kku, *rku, *vvt, *vecu;
    __nv_bfloat16* bdh;
    float *vv, *xb;
    cudaGetSymbolAddress((void**)&wu, g_wu);
    cudaGetSymbolAddress((void**)&ru, g_ru);
    cudaGetSymbolAddress((void**)&WqkvT, g_WqkvT);
    cudaGetSymbolAddress((void**)&WrfwT, g_WrfwT);
    cudaGetSymbolAddress((void**)&WrbwT, g_WrbwT);
    cudaGetSymbolAddress((void**)&WoT, g_WoT);
    cudaGetSymbolAddress((void**)&q1u, g_q1u);
    cudaGetSymbolAddress((void**)&q2u, g_q2u);
    cudaGetSymbolAddress((void**)&kku, g_kku);
    cudaGetSymbolAddress((void**)&vv, g_vv);
    cudaGetSymbolAddress((void**)&vvt, g_vvt);
    cudaGetSymbolAddress((void**)&rku, g_rku);
    cudaGetSymbolAddress((void**)&bdh, g_bdh);
    cudaGetSymbolAddress((void**)&vecu, g_vecu);
    cudaGetSymbolAddress((void**)&xb, g_x);

    prep_k<<<7682, 256>>>(w, wu, r, ru, Wqkv, WqkvT, Wrfw, WrfwT,
                          Wrbw, WrbwT, Wo, WoT, rku + 2047 * 512);

    int bg_smem = 2 * 8192 * 4;  // 64 KB
    cudaFuncSetAttribute(gemms_k, cudaFuncAttributeMaxDynamicSharedMemorySize, bg_smem);
    cudaFuncSetAttribute(wo_k, cudaFuncAttributeMaxDynamicSharedMemorySize, bg_smem);

    gemms_k<<<512, 256, bg_smem>>>(wu, WqkvT, rwb, rrb, q1u, q2u, kku, vv,
                                   ru, WrfwT, WrbwT, rku, rku + 2046 * 512);

    int vb_smem = 130 * 256 + 1024;
    cudaFuncSetAttribute(vtbd_k, cudaFuncAttributeMaxDynamicSharedMemorySize, vb_smem);
    vtbd_k<<<2560, 256, vb_smem>>>(q2u, rku, (unsigned*)bdh, vv, vvt, mask);

    int fl_smem = (4096 + 3 * 2048 + 3 * 2048) * 4;  // 64 KB
    cudaFuncSetAttribute(flash_k, cudaFuncAttributeMaxDynamicSharedMemorySize, fl_smem);
    flash_k<<<dim3(8, 32), 256, fl_smem>>>(q1u, kku, vvt, bdh, vecu);

    wo_k<<<dim3(8, 16), 256, bg_smem>>>(vecu, WoT, xb);

    ln_k<<<2048, 256>>>(w, xb, lng, lnb, out);
}